// round 1
// baseline (speedup 1.0000x reference)
#include <cuda_runtime.h>
#include <math.h>

#define BATCH  2
#define SEQ    2048
#define DIM    1024
#define NH     16
#define NG     4
#define GRP    4
#define HDIM   64
#define FF     4096
#define NL     8
#define VOCAB  32000
#define WIN    1024
#define EPS    1e-6f
#define NTOK   (BATCH*SEQ)   // 4096

// ---------------- scratch (static device globals; no allocation) ----------------
__device__ float g_x  [NTOK*DIM];
__device__ float g_h  [NTOK*DIM];
__device__ float g_q  [NTOK*NH*HDIM];
__device__ float g_k  [NTOK*NG*HDIM];
__device__ float g_v  [NTOK*NG*HDIM];
__device__ float g_att[NTOK*NH*HDIM];
__device__ float g_t  [NTOK*DIM];
__device__ float g_f1 [NTOK*FF];
__device__ float g_f2 [NTOK*FF];

// ---------------- embedding gather ----------------
__global__ void embed_kernel(const int* __restrict__ ids,
                             const float* __restrict__ emb,
                             float* __restrict__ x) {
    int t = blockIdx.x;
    int id = ids[t];
    const float* e = emb + (size_t)id * DIM;
    float* xp = x + (size_t)t * DIM;
    for (int d = threadIdx.x; d < DIM; d += blockDim.x)
        xp[d] = e[d] * 32.0f;   // sqrt(1024)
}

// ---------------- rmsnorm: out = rmsnorm(in, scale) ----------------
__global__ __launch_bounds__(256) void rmsnorm_kernel(const float* __restrict__ in,
                                                      const float* __restrict__ scale,
                                                      float* __restrict__ out) {
    const int t = blockIdx.x;
    const float* xp = in + (size_t)t * DIM;
    float ss = 0.f;
    for (int d = threadIdx.x; d < DIM; d += 256) { float v = xp[d]; ss += v * v; }
    __shared__ float red[256];
    red[threadIdx.x] = ss; __syncthreads();
    for (int o = 128; o > 0; o >>= 1) {
        if (threadIdx.x < o) red[threadIdx.x] += red[threadIdx.x + o];
        __syncthreads();
    }
    const float r = rsqrtf(red[0] * (1.0f / DIM) + EPS);
    float* op = out + (size_t)t * DIM;
    for (int d = threadIdx.x; d < DIM; d += 256)
        op[d] = xp[d] * r * (1.0f + scale[d]);
}

// ---------------- x += rmsnorm(tin, scale) ----------------
__global__ __launch_bounds__(256) void addrms_kernel(float* __restrict__ x,
                                                     const float* __restrict__ tin,
                                                     const float* __restrict__ scale) {
    const int t = blockIdx.x;
    const float* tp = tin + (size_t)t * DIM;
    float ss = 0.f;
    for (int d = threadIdx.x; d < DIM; d += 256) { float v = tp[d]; ss += v * v; }
    __shared__ float red[256];
    red[threadIdx.x] = ss; __syncthreads();
    for (int o = 128; o > 0; o >>= 1) {
        if (threadIdx.x < o) red[threadIdx.x] += red[threadIdx.x + o];
        __syncthreads();
    }
    const float r = rsqrtf(red[0] * (1.0f / DIM) + EPS);
    float* xp = x + (size_t)t * DIM;
    for (int d = threadIdx.x; d < DIM; d += 256)
        xp[d] += tp[d] * r * (1.0f + scale[d]);
}

// ---------------- per-head rmsnorm + rope (in place) ----------------
__global__ __launch_bounds__(64) void qkrope_kernel(float* __restrict__ x,
                                                    const float* __restrict__ scale,
                                                    const float* __restrict__ cosb,
                                                    const float* __restrict__ sinb,
                                                    int nheads) {
    const int token = blockIdx.x;       // b*SEQ + s
    const int h = blockIdx.y;
    const int pos = token % SEQ;
    const int d = threadIdx.x;
    float* xp = x + ((size_t)token * nheads + h) * HDIM;
    const float val = xp[d];
    __shared__ float sh[HDIM];
    sh[d] = val * val;
    __syncthreads();
    for (int o = 32; o > 0; o >>= 1) {
        if (d < o) sh[d] += sh[d + o];
        __syncthreads();
    }
    const float r = rsqrtf(sh[0] * (1.0f / HDIM) + EPS);
    __syncthreads();
    const float nv = val * r * (1.0f + scale[d]);
    sh[d] = nv;
    __syncthreads();
    const float rot = (d < 32) ? -sh[d + 32] : sh[d - 32];
    xp[d] = nv * cosb[pos * HDIM + d] + rot * sinb[pos * HDIM + d];
}

// ---------------- attention: one block per (query, batch, head) ----------------
// q: [b,s,NH,HDIM], k/v: [b,s,NG,HDIM], out: [b,s,NH*HDIM]. window=0 -> full causal.
__global__ __launch_bounds__(128) void attn_kernel(const float* __restrict__ q,
                                                   const float* __restrict__ kx,
                                                   const float* __restrict__ vx,
                                                   float* __restrict__ out,
                                                   int window) {
    const int qi = blockIdx.x;
    const int b  = blockIdx.y;
    const int h  = blockIdx.z;
    const int g  = h / GRP;
    const int tid = threadIdx.x;

    __shared__ float sc[SEQ];
    __shared__ float qs[HDIM];
    __shared__ float red[128];
    __shared__ float part[HDIM];

    if (tid < HDIM)
        qs[tid] = q[(((size_t)b * SEQ + qi) * NH + h) * HDIM + tid] * 0.125f; // HD^-0.5

    int jlo = 0;
    if (window > 0) { int t = qi - window; if (t > 0) jlo = t; }
    const int jn = qi - jlo + 1;
    __syncthreads();

    // phase 1: scores + max
    float lmax = -1e30f;
    const float* kbase = kx + ((size_t)b * SEQ * NG + g) * HDIM;
    for (int jj = tid; jj < jn; jj += 128) {
        const float* kp = kbase + (size_t)(jlo + jj) * NG * HDIM;
        float dot = 0.f;
#pragma unroll
        for (int d = 0; d < HDIM; d += 4) {
            float4 k4 = *(const float4*)(kp + d);
            dot += qs[d] * k4.x + qs[d+1] * k4.y + qs[d+2] * k4.z + qs[d+3] * k4.w;
        }
        sc[jj] = dot;
        lmax = fmaxf(lmax, dot);
    }
    red[tid] = lmax; __syncthreads();
    for (int o = 64; o > 0; o >>= 1) {
        if (tid < o) red[tid] = fmaxf(red[tid], red[tid + o]);
        __syncthreads();
    }
    const float mx = red[0];
    __syncthreads();

    // phase 2: exp + sum
    float lsum = 0.f;
    for (int jj = tid; jj < jn; jj += 128) {
        float e = __expf(sc[jj] - mx);
        sc[jj] = e;
        lsum += e;
    }
    red[tid] = lsum; __syncthreads();
    for (int o = 64; o > 0; o >>= 1) {
        if (tid < o) red[tid] += red[tid + o];
        __syncthreads();
    }
    const float inv = 1.0f / red[0];
    __syncthreads();

    // phase 3: weighted sum of V; 2-way split over keys, 64 dims
    const int d = tid & 63;
    const int half = tid >> 6;
    const float* vbase = vx + ((size_t)b * SEQ * NG + g) * HDIM + d;
    float acc = 0.f;
    for (int jj = half; jj < jn; jj += 2)
        acc += sc[jj] * vbase[(size_t)(jlo + jj) * NG * HDIM];
    if (half) part[d] = acc;
    __syncthreads();
    if (!half)
        out[(((size_t)b * SEQ + qi) * NH + h) * HDIM + d] = (acc + part[d]) * inv;
}

// ---------------- silu(a) * b -> a ----------------
__global__ void silu_mul_kernel(float* __restrict__ a, const float* __restrict__ b, int n) {
    int i = blockIdx.x * 256 + threadIdx.x;
    if (i < n) {
        float v = a[i];
        float s = v / (1.0f + __expf(-v));
        a[i] = s * b[i];
    }
}

// ---------------- SGEMM 128x128x8, 8x8 microtile, fp32 ----------------
#define BM 128
#define BN 128
#define BK 8
#define TM 8
#define TN 8

// C[M,N] = A[M,K] @ B[K,N]   (all row-major; M%128==0, N%128==0, K%8==0)
__global__ __launch_bounds__(256) void sgemm_nn(const float* __restrict__ A,
                                                const float* __restrict__ B,
                                                float* __restrict__ C,
                                                int M, int N, int K) {
    __shared__ float As[BK][BM];
    __shared__ float Bs[BK][BN];
    const int bm = blockIdx.y * BM;
    const int bn = blockIdx.x * BN;
    const int tid = threadIdx.x;
    const int tx = tid & 15, ty = tid >> 4;
    const int arow = tid >> 1;
    const int acol = (tid & 1) * 4;
    const int brow = tid >> 5;
    const int bcol = (tid & 31) * 4;

    float acc[TM][TN] = {};
    const float* Aptr = A + (size_t)(bm + arow) * K + acol;
    const float* Bptr = B + (size_t)brow * N + bn + bcol;

    for (int k0 = 0; k0 < K; k0 += BK) {
        float4 a4 = *(const float4*)(Aptr + k0);
        As[acol + 0][arow] = a4.x;
        As[acol + 1][arow] = a4.y;
        As[acol + 2][arow] = a4.z;
        As[acol + 3][arow] = a4.w;
        float4 b4 = *(const float4*)(Bptr + (size_t)k0 * N);
        *(float4*)&Bs[brow][bcol] = b4;
        __syncthreads();
#pragma unroll
        for (int kk = 0; kk < BK; kk++) {
            float4 a0 = *(const float4*)&As[kk][ty * TM];
            float4 a1 = *(const float4*)&As[kk][ty * TM + 4];
            float4 b0 = *(const float4*)&Bs[kk][tx * TN];
            float4 b1 = *(const float4*)&Bs[kk][tx * TN + 4];
            float ar[8] = {a0.x, a0.y, a0.z, a0.w, a1.x, a1.y, a1.z, a1.w};
            float br[8] = {b0.x, b0.y, b0.z, b0.w, b1.x, b1.y, b1.z, b1.w};
#pragma unroll
            for (int i = 0; i < TM; i++)
#pragma unroll
                for (int j = 0; j < TN; j++)
                    acc[i][j] += ar[i] * br[j];
        }
        __syncthreads();
    }
#pragma unroll
    for (int i = 0; i < TM; i++) {
        float* cp = C + (size_t)(bm + ty * TM + i) * N + bn + tx * TN;
        *(float4*)cp       = make_float4(acc[i][0], acc[i][1], acc[i][2], acc[i][3]);
        *(float4*)(cp + 4) = make_float4(acc[i][4], acc[i][5], acc[i][6], acc[i][7]);
    }
}

// C[M,N] = A[M,K] @ B^T where B is [N,K] row-major (logits vs tok_emb)
__global__ __launch_bounds__(256) void sgemm_nt(const float* __restrict__ A,
                                                const float* __restrict__ B,
                                                float* __restrict__ C,
                                                int M, int N, int K) {
    __shared__ float As[BK][BM];
    __shared__ float Bs[BK][BN];
    const int bm = blockIdx.y * BM;
    const int bn = blockIdx.x * BN;
    const int tid = threadIdx.x;
    const int tx = tid & 15, ty = tid >> 4;
    const int arow = tid >> 1;
    const int acol = (tid & 1) * 4;

    float acc[TM][TN] = {};
    const float* Aptr = A + (size_t)(bm + arow) * K + acol;
    const float* Bptr = B + (size_t)(bn + arow) * K + acol;

    for (int k0 = 0; k0 < K; k0 += BK) {
        float4 a4 = *(const float4*)(Aptr + k0);
        As[acol + 0][arow] = a4.x;
        As[acol + 1][arow] = a4.y;
        As[acol + 2][arow] = a4.z;
        As[acol + 3][arow] = a4.w;
        float4 b4 = *(const float4*)(Bptr + k0);
        Bs[acol + 0][arow] = b4.x;
        Bs[acol + 1][arow] = b4.y;
        Bs[acol + 2][arow] = b4.z;
        Bs[acol + 3][arow] = b4.w;
        __syncthreads();
#pragma unroll
        for (int kk = 0; kk < BK; kk++) {
            float4 a0 = *(const float4*)&As[kk][ty * TM];
            float4 a1 = *(const float4*)&As[kk][ty * TM + 4];
            float4 b0 = *(const float4*)&Bs[kk][tx * TN];
            float4 b1 = *(const float4*)&Bs[kk][tx * TN + 4];
            float ar[8] = {a0.x, a0.y, a0.z, a0.w, a1.x, a1.y, a1.z, a1.w};
            float br[8] = {b0.x, b0.y, b0.z, b0.w, b1.x, b1.y, b1.z, b1.w};
#pragma unroll
            for (int i = 0; i < TM; i++)
#pragma unroll
                for (int j = 0; j < TN; j++)
                    acc[i][j] += ar[i] * br[j];
        }
        __syncthreads();
    }
#pragma unroll
    for (int i = 0; i < TM; i++) {
        float* cp = C + (size_t)(bm + ty * TM + i) * N + bn + tx * TN;
        *(float4*)cp       = make_float4(acc[i][0], acc[i][1], acc[i][2], acc[i][3]);
        *(float4*)(cp + 4) = make_float4(acc[i][4], acc[i][5], acc[i][6], acc[i][7]);
    }
}

// ---------------- driver ----------------
extern "C" void kernel_launch(void* const* d_in, const int* in_sizes, int n_in,
                              void* d_out, int out_size) {
    const int*   ids = (const int*)  d_in[0];
    const float* emb = (const float*)d_in[1];
    const float* Wq  = (const float*)d_in[2];
    const float* Wk  = (const float*)d_in[3];
    const float* Wv  = (const float*)d_in[4];
    const float* Wo  = (const float*)d_in[5];
    const float* W1  = (const float*)d_in[6];
    const float* W2  = (const float*)d_in[7];
    const float* W3  = (const float*)d_in[8];
    const float* n1  = (const float*)d_in[9];
    const float* n2  = (const float*)d_in[10];
    const float* n3  = (const float*)d_in[11];
    const float* n4  = (const float*)d_in[12];
    const float* qn  = (const float*)d_in[13];
    const float* kn  = (const float*)d_in[14];
    const float* nf  = (const float*)d_in[15];
    const float* cosb = (const float*)d_in[16];
    const float* sinb = (const float*)d_in[17];
    float* out = (float*)d_out;

    float *x, *h, *q, *k, *v, *att, *t, *f1, *f2;
    cudaGetSymbolAddress((void**)&x,   g_x);
    cudaGetSymbolAddress((void**)&h,   g_h);
    cudaGetSymbolAddress((void**)&q,   g_q);
    cudaGetSymbolAddress((void**)&k,   g_k);
    cudaGetSymbolAddress((void**)&v,   g_v);
    cudaGetSymbolAddress((void**)&att, g_att);
    cudaGetSymbolAddress((void**)&t,   g_t);
    cudaGetSymbolAddress((void**)&f1,  g_f1);
    cudaGetSymbolAddress((void**)&f2,  g_f2);

    embed_kernel<<<NTOK, 256>>>(ids, emb, x);

    for (int l = 0; l < NL; l++) {
        const int window = (l < NL - 4) ? WIN : 0;

        rmsnorm_kernel<<<NTOK, 256>>>(x, n1 + (size_t)l * DIM, h);

        sgemm_nn<<<dim3((NH*HDIM)/BN, NTOK/BM), 256>>>(h, Wq + (size_t)l * DIM * NH * HDIM, q, NTOK, NH*HDIM, DIM);
        sgemm_nn<<<dim3((NG*HDIM)/BN, NTOK/BM), 256>>>(h, Wk + (size_t)l * DIM * NG * HDIM, k, NTOK, NG*HDIM, DIM);
        sgemm_nn<<<dim3((NG*HDIM)/BN, NTOK/BM), 256>>>(h, Wv + (size_t)l * DIM * NG * HDIM, v, NTOK, NG*HDIM, DIM);

        qkrope_kernel<<<dim3(NTOK, NH), 64>>>(q, qn + (size_t)l * HDIM, cosb, sinb, NH);
        qkrope_kernel<<<dim3(NTOK, NG), 64>>>(k, kn + (size_t)l * HDIM, cosb, sinb, NG);

        attn_kernel<<<dim3(SEQ, BATCH, NH), 128>>>(q, k, v, att, window);

        sgemm_nn<<<dim3(DIM/BN, NTOK/BM), 256>>>(att, Wo + (size_t)l * NH * HDIM * DIM, t, NTOK, DIM, NH*HDIM);
        addrms_kernel<<<NTOK, 256>>>(x, t, n2 + (size_t)l * DIM);

        rmsnorm_kernel<<<NTOK, 256>>>(x, n3 + (size_t)l * DIM, h);
        sgemm_nn<<<dim3(FF/BN, NTOK/BM), 256>>>(h, W1 + (size_t)l * DIM * FF, f1, NTOK, FF, DIM);
        sgemm_nn<<<dim3(FF/BN, NTOK/BM), 256>>>(h, W2 + (size_t)l * DIM * FF, f2, NTOK, FF, DIM);
        silu_mul_kernel<<<(NTOK * FF) / 256, 256>>>(f1, f2, NTOK * FF);
        sgemm_nn<<<dim3(DIM/BN, NTOK/BM), 256>>>(f1, W3 + (size_t)l * FF * DIM, t, NTOK, DIM, FF);
        addrms_kernel<<<NTOK, 256>>>(x, t, n4 + (size_t)l * DIM);
    }

    rmsnorm_kernel<<<NTOK, 256>>>(x, nf, h);
    sgemm_nt<<<dim3(VOCAB/BN, NTOK/BM), 256>>>(h, emb, out, NTOK, VOCAB, DIM);
}

// round 3
// speedup vs baseline: 1.5410x; 1.5410x over previous
#include <cuda_runtime.h>
#include <cuda_bf16.h>
#include <math.h>
#include <stdint.h>

#define BATCH  2
#define SEQ    2048
#define DIM    1024
#define NH     16
#define NG     4
#define GRP    4
#define HDIM   64
#define FF     4096
#define NL     8
#define VOCAB  32000
#define WIN    1024
#define EPS    1e-6f
#define NTOK   (BATCH*SEQ)   // 4096

// ======================= scratch =======================
__device__ float g_x  [NTOK*DIM];
__device__ float g_q  [NTOK*NH*HDIM];
__device__ float g_k  [NTOK*NG*HDIM];
__device__ float g_v  [NTOK*NG*HDIM];
__device__ float g_t  [NTOK*DIM];
__device__ float g_f1 [NTOK*FF];
__device__ float g_f2 [NTOK*FF];

__device__ __align__(128) __nv_bfloat16 g_a_h[NTOK*FF];
__device__ __align__(128) __nv_bfloat16 g_a_l[NTOK*FF];
__device__ __align__(128) __nv_bfloat16 g_wqt_h[NL*1024*1024];
__device__ __align__(128) __nv_bfloat16 g_wqt_l[NL*1024*1024];
__device__ __align__(128) __nv_bfloat16 g_wkt_h[NL*256*1024];
__device__ __align__(128) __nv_bfloat16 g_wkt_l[NL*256*1024];
__device__ __align__(128) __nv_bfloat16 g_wvt_h[NL*256*1024];
__device__ __align__(128) __nv_bfloat16 g_wvt_l[NL*256*1024];
__device__ __align__(128) __nv_bfloat16 g_wot_h[NL*1024*1024];
__device__ __align__(128) __nv_bfloat16 g_wot_l[NL*1024*1024];
__device__ __align__(128) __nv_bfloat16 g_w1t_h[NL*4096*1024];
__device__ __align__(128) __nv_bfloat16 g_w1t_l[NL*4096*1024];
__device__ __align__(128) __nv_bfloat16 g_w2t_h[NL*4096*1024];
__device__ __align__(128) __nv_bfloat16 g_w2t_l[NL*4096*1024];
__device__ __align__(128) __nv_bfloat16 g_w3t_h[NL*1024*4096];
__device__ __align__(128) __nv_bfloat16 g_w3t_l[NL*1024*4096];
__device__ __align__(128) __nv_bfloat16 g_emb_h[VOCAB*DIM];
__device__ __align__(128) __nv_bfloat16 g_emb_l[VOCAB*DIM];

// ======================= small kernels =======================
__global__ void embed_kernel(const int* __restrict__ ids,
                             const float* __restrict__ emb,
                             float* __restrict__ x) {
    int t = blockIdx.x;
    int id = ids[t];
    const float* e = emb + (size_t)id * DIM;
    float* xp = x + (size_t)t * DIM;
    for (int d = threadIdx.x; d < DIM; d += blockDim.x)
        xp[d] = e[d] * 32.0f;
}

__global__ void split_kernel(const float* __restrict__ in,
                             __nv_bfloat16* __restrict__ oh,
                             __nv_bfloat16* __restrict__ ol, int n) {
    int i = blockIdx.x * 256 + threadIdx.x;
    if (i < n) {
        float v = in[i];
        __nv_bfloat16 h = __float2bfloat16(v);
        oh[i] = h;
        ol[i] = __float2bfloat16(v - __bfloat162float(h));
    }
}

// transpose + split: W [L,K,N] fp32 -> out [L,N,K] bf16 hi/lo
__global__ void wconv_kernel(const float* __restrict__ W,
                             __nv_bfloat16* __restrict__ oh,
                             __nv_bfloat16* __restrict__ ol, int K, int N) {
    __shared__ float t[32][33];
    int l = blockIdx.z;
    const float* Wl = W + (size_t)l * K * N;
    size_t ob = (size_t)l * K * N;
    int n0 = blockIdx.x * 32, k0 = blockIdx.y * 32;
    int tx = threadIdx.x, ty = threadIdx.y;
#pragma unroll
    for (int r = 0; r < 32; r += 8)
        t[ty + r][tx] = Wl[(size_t)(k0 + ty + r) * N + n0 + tx];
    __syncthreads();
#pragma unroll
    for (int r = 0; r < 32; r += 8) {
        float v = t[tx][ty + r];
        __nv_bfloat16 h = __float2bfloat16(v);
        size_t o = ob + (size_t)(n0 + ty + r) * K + k0 + tx;
        oh[o] = h;
        ol[o] = __float2bfloat16(v - __bfloat162float(h));
    }
}

__global__ __launch_bounds__(256) void rmsnorm_split_kernel(const float* __restrict__ in,
                                                            const float* __restrict__ scale,
                                                            __nv_bfloat16* __restrict__ oh,
                                                            __nv_bfloat16* __restrict__ ol) {
    const int t = blockIdx.x;
    const float* xp = in + (size_t)t * DIM;
    float ss = 0.f;
    for (int d = threadIdx.x; d < DIM; d += 256) { float v = xp[d]; ss += v * v; }
    __shared__ float red[256];
    red[threadIdx.x] = ss; __syncthreads();
    for (int o = 128; o > 0; o >>= 1) {
        if (threadIdx.x < o) red[threadIdx.x] += red[threadIdx.x + o];
        __syncthreads();
    }
    const float r = rsqrtf(red[0] * (1.0f / DIM) + EPS);
    for (int d = threadIdx.x; d < DIM; d += 256) {
        float v = xp[d] * r * (1.0f + scale[d]);
        __nv_bfloat16 h = __float2bfloat16(v);
        oh[(size_t)t * DIM + d] = h;
        ol[(size_t)t * DIM + d] = __float2bfloat16(v - __bfloat162float(h));
    }
}

__global__ __launch_bounds__(256) void addrms_kernel(float* __restrict__ x,
                                                     const float* __restrict__ tin,
                                                     const float* __restrict__ scale) {
    const int t = blockIdx.x;
    const float* tp = tin + (size_t)t * DIM;
    float ss = 0.f;
    for (int d = threadIdx.x; d < DIM; d += 256) { float v = tp[d]; ss += v * v; }
    __shared__ float red[256];
    red[threadIdx.x] = ss; __syncthreads();
    for (int o = 128; o > 0; o >>= 1) {
        if (threadIdx.x < o) red[threadIdx.x] += red[threadIdx.x + o];
        __syncthreads();
    }
    const float r = rsqrtf(red[0] * (1.0f / DIM) + EPS);
    float* xp = x + (size_t)t * DIM;
    for (int d = threadIdx.x; d < DIM; d += 256)
        xp[d] += tp[d] * r * (1.0f + scale[d]);
}

__global__ __launch_bounds__(64) void qkrope_kernel(float* __restrict__ x,
                                                    const float* __restrict__ scale,
                                                    const float* __restrict__ cosb,
                                                    const float* __restrict__ sinb,
                                                    int nheads) {
    const int token = blockIdx.x;
    const int h = blockIdx.y;
    const int pos = token % SEQ;
    const int d = threadIdx.x;
    float* xp = x + ((size_t)token * nheads + h) * HDIM;
    const float val = xp[d];
    __shared__ float sh[HDIM];
    sh[d] = val * val;
    __syncthreads();
    for (int o = 32; o > 0; o >>= 1) {
        if (d < o) sh[d] += sh[d + o];
        __syncthreads();
    }
    const float r = rsqrtf(sh[0] * (1.0f / HDIM) + EPS);
    __syncthreads();
    const float nv = val * r * (1.0f + scale[d]);
    sh[d] = nv;
    __syncthreads();
    const float rot = (d < 32) ? -sh[d + 32] : sh[d - 32];
    xp[d] = nv * cosb[pos * HDIM + d] + rot * sinb[pos * HDIM + d];
}

// attention -> split bf16 output
__global__ __launch_bounds__(128) void attn_kernel(const float* __restrict__ q,
                                                   const float* __restrict__ kx,
                                                   const float* __restrict__ vx,
                                                   __nv_bfloat16* __restrict__ oh,
                                                   __nv_bfloat16* __restrict__ ol,
                                                   int window) {
    const int qi = blockIdx.x;
    const int b  = blockIdx.y;
    const int h  = blockIdx.z;
    const int g  = h / GRP;
    const int tid = threadIdx.x;

    __shared__ float sc[SEQ];
    __shared__ float qs[HDIM];
    __shared__ float red[128];
    __shared__ float part[HDIM];

    if (tid < HDIM)
        qs[tid] = q[(((size_t)b * SEQ + qi) * NH + h) * HDIM + tid] * 0.125f;

    int jlo = 0;
    if (window > 0) { int t = qi - window; if (t > 0) jlo = t; }
    const int jn = qi - jlo + 1;
    __syncthreads();

    float lmax = -1e30f;
    const float* kbase = kx + ((size_t)b * SEQ * NG + g) * HDIM;
    for (int jj = tid; jj < jn; jj += 128) {
        const float* kp = kbase + (size_t)(jlo + jj) * NG * HDIM;
        float dot = 0.f;
#pragma unroll
        for (int d = 0; d < HDIM; d += 4) {
            float4 k4 = *(const float4*)(kp + d);
            dot += qs[d] * k4.x + qs[d+1] * k4.y + qs[d+2] * k4.z + qs[d+3] * k4.w;
        }
        sc[jj] = dot;
        lmax = fmaxf(lmax, dot);
    }
    red[tid] = lmax; __syncthreads();
    for (int o = 64; o > 0; o >>= 1) {
        if (tid < o) red[tid] = fmaxf(red[tid], red[tid + o]);
        __syncthreads();
    }
    const float mx = red[0];
    __syncthreads();

    float lsum = 0.f;
    for (int jj = tid; jj < jn; jj += 128) {
        float e = __expf(sc[jj] - mx);
        sc[jj] = e;
        lsum += e;
    }
    red[tid] = lsum; __syncthreads();
    for (int o = 64; o > 0; o >>= 1) {
        if (tid < o) red[tid] += red[tid + o];
        __syncthreads();
    }
    const float inv = 1.0f / red[0];
    __syncthreads();

    const int d = tid & 63;
    const int half = tid >> 6;
    const float* vbase = vx + ((size_t)b * SEQ * NG + g) * HDIM + d;
    float acc = 0.f;
    for (int jj = half; jj < jn; jj += 2)
        acc += sc[jj] * vbase[(size_t)(jlo + jj) * NG * HDIM];
    if (half) part[d] = acc;
    __syncthreads();
    if (!half) {
        float o = (acc + part[d]) * inv;
        size_t idx = (((size_t)b * SEQ + qi) * NH + h) * HDIM + d;
        __nv_bfloat16 hv = __float2bfloat16(o);
        oh[idx] = hv;
        ol[idx] = __float2bfloat16(o - __bfloat162float(hv));
    }
}

__global__ void silu_split_kernel(const float* __restrict__ a,
                                  const float* __restrict__ b,
                                  __nv_bfloat16* __restrict__ oh,
                                  __nv_bfloat16* __restrict__ ol, int n) {
    int i = blockIdx.x * 256 + threadIdx.x;
    if (i < n) {
        float v = a[i];
        float s = v / (1.0f + __expf(-v)) * b[i];
        __nv_bfloat16 h = __float2bfloat16(s);
        oh[i] = h;
        ol[i] = __float2bfloat16(s - __bfloat162float(h));
    }
}

// ======================= mma.sync bf16 GEMM =======================
// C[M,N] = (Ah+Al)[M,K] @ (Bh+Bl)[N,K]^T with 3 passes: AhBh + AlBh + AhBl.
// CTA tile 128x128, BK=32, 8 warps (warp tile 32x64), 3-stage cp.async pipeline.
// smem tile layout: row r (64B of bf16), 16B unit u stored at u ^ ((r>>1)&3).
#define SSTG      32768          // Ah(8K) + Al(8K) + Bh(8K) + Bl(8K)
#define GSMEM     (3*SSTG)       // 96 KB

__device__ __forceinline__ uint32_t smem_u32(const void* p) {
    uint32_t a;
    asm("{ .reg .u64 t; cvta.to.shared.u64 t, %1; cvt.u32.u64 %0, t; }" : "=r"(a) : "l"(p));
    return a;
}
__device__ __forceinline__ void cp16(uint32_t s, const void* g) {
    asm volatile("cp.async.cg.shared.global [%0], [%1], 16;" :: "r"(s), "l"(g));
}
#define LDMX4(r0, r1, r2, r3, addr) \
    asm volatile("ldmatrix.sync.aligned.m8n8.x4.shared.b16 {%0,%1,%2,%3}, [%4];" \
        : "=r"(r0), "=r"(r1), "=r"(r2), "=r"(r3) : "r"(addr))
#define MMA16816(d, a, b) \
    asm volatile("mma.sync.aligned.m16n8k16.row.col.f32.bf16.bf16.f32 " \
        "{%0,%1,%2,%3}, {%4,%5,%6,%7}, {%8,%9}, {%0,%1,%2,%3};" \
        : "+f"((d)[0]), "+f"((d)[1]), "+f"((d)[2]), "+f"((d)[3]) \
        : "r"((a)[0]), "r"((a)[1]), "r"((a)[2]), "r"((a)[3]), "r"((b)[0]), "r"((b)[1]))

__device__ __forceinline__ void stage_load(uint32_t st,
                                           const __nv_bfloat16* Ah, const __nv_bfloat16* Al,
                                           const __nv_bfloat16* Bh, const __nv_bfloat16* Bl,
                                           int m0, int n0, int k0, int K, int tid) {
#pragma unroll
    for (int c = tid; c < 512; c += 256) {
        int r = c >> 2, u = c & 3;
        uint32_t off = r * 64 + ((u ^ ((r >> 1) & 3)) << 4);
        size_t ga = (size_t)(m0 + r) * K + k0 + u * 8;
        size_t gb = (size_t)(n0 + r) * K + k0 + u * 8;
        cp16(st + off,          Ah + ga);
        cp16(st + 8192  + off,  Al + ga);
        cp16(st + 16384 + off,  Bh + gb);
        cp16(st + 24576 + off,  Bl + gb);
    }
    asm volatile("cp.async.commit_group;" ::: "memory");
}

__global__ __launch_bounds__(256, 1) void gemm_bf16(
    const __nv_bfloat16* __restrict__ Ah, const __nv_bfloat16* __restrict__ Al,
    const __nv_bfloat16* __restrict__ Bh, const __nv_bfloat16* __restrict__ Bl,
    float* __restrict__ C, int N, int K)
{
    extern __shared__ __align__(128) char smem[];
    const uint32_t sb = smem_u32(smem);
    const int tid = threadIdx.x;
    const int lane = tid & 31;
    const int w = tid >> 5;
    const int wm = w & 3;          // M warp block (32 rows)
    const int wn = w >> 2;         // N warp block (64 cols)
    const int m0 = blockIdx.x * 128;
    const int n0 = blockIdx.y * 128;
    const int niter = K >> 5;

    float acc[2][8][4] = {};

    stage_load(sb,          Ah, Al, Bh, Bl, m0, n0, 0,  K, tid);
    stage_load(sb + SSTG,   Ah, Al, Bh, Bl, m0, n0, 32, K, tid);

    // precomputed fragment smem offsets (swizzled)
    // A: row = wm*32 + mb*16 + (lane&15), unit = ks*2 + (lane>>4)
    // B: mat = lane>>3; row = wn*64 + (2q + (mat>>1))*8 + (lane&7); unit = ks*2 + (mat&1)
    const int a_r = wm * 32 + (lane & 15);
    const int a_uadd = lane >> 4;
    const int b_mat = lane >> 3;
    const int b_r0 = wn * 64 + ((b_mat >> 1) << 3) + (lane & 7);
    const int b_uadd = b_mat & 1;

    for (int it = 0; it < niter; it++) {
        if (it + 2 < niter) { asm volatile("cp.async.wait_group 1;" ::: "memory"); }
        else                { asm volatile("cp.async.wait_group 0;" ::: "memory"); }
        __syncthreads();
        if (it + 2 < niter)
            stage_load(sb + ((it + 2) % 3) * SSTG, Ah, Al, Bh, Bl, m0, n0, (it + 2) * 32, K, tid);

        const uint32_t st = sb + (it % 3) * SSTG;
#pragma unroll
        for (int ks = 0; ks < 2; ks++) {
            uint32_t ah[2][4], al[2][4], bh[8][2], bl[8][2];
#pragma unroll
            for (int mb = 0; mb < 2; mb++) {
                int r = a_r + mb * 16;
                int u = ks * 2 + a_uadd;
                uint32_t off = r * 64 + ((u ^ ((r >> 1) & 3)) << 4);
                LDMX4(ah[mb][0], ah[mb][1], ah[mb][2], ah[mb][3], st + off);
                LDMX4(al[mb][0], al[mb][1], al[mb][2], al[mb][3], st + 8192 + off);
            }
#pragma unroll
            for (int qd = 0; qd < 4; qd++) {
                int r = b_r0 + qd * 16;
                int u = ks * 2 + b_uadd;
                uint32_t off = r * 64 + ((u ^ ((r >> 1) & 3)) << 4);
                uint32_t t0, t1, t2, t3;
                LDMX4(t0, t1, t2, t3, st + 16384 + off);
                bh[2*qd][0] = t0; bh[2*qd][1] = t1; bh[2*qd+1][0] = t2; bh[2*qd+1][1] = t3;
                LDMX4(t0, t1, t2, t3, st + 24576 + off);
                bl[2*qd][0] = t0; bl[2*qd][1] = t1; bl[2*qd+1][0] = t2; bl[2*qd+1][1] = t3;
            }
#pragma unroll
            for (int mb = 0; mb < 2; mb++)
#pragma unroll
                for (int nb = 0; nb < 8; nb++) {
                    MMA16816(acc[mb][nb], ah[mb], bh[nb]);
                    MMA16816(acc[mb][nb], al[mb], bh[nb]);
                    MMA16816(acc[mb][nb], ah[mb], bl[nb]);
                }
        }
    }

    // epilogue
#pragma unroll
    for (int mb = 0; mb < 2; mb++) {
        int row = m0 + wm * 32 + mb * 16 + (lane >> 2);
#pragma unroll
        for (int nb = 0; nb < 8; nb++) {
            int col = n0 + wn * 64 + nb * 8 + 2 * (lane & 3);
            *(float2*)(C + (size_t)row * N + col)       = make_float2(acc[mb][nb][0], acc[mb][nb][1]);
            *(float2*)(C + (size_t)(row + 8) * N + col) = make_float2(acc[mb][nb][2], acc[mb][nb][3]);
        }
    }
}

// ======================= host driver =======================
extern "C" void kernel_launch(void* const* d_in, const int* in_sizes, int n_in,
                              void* d_out, int out_size) {
    const int*   ids = (const int*)  d_in[0];
    const float* emb = (const float*)d_in[1];
    const float* Wq  = (const float*)d_in[2];
    const float* Wk  = (const float*)d_in[3];
    const float* Wv  = (const float*)d_in[4];
    const float* Wo  = (const float*)d_in[5];
    const float* W1  = (const float*)d_in[6];
    const float* W2  = (const float*)d_in[7];
    const float* W3  = (const float*)d_in[8];
    const float* n1  = (const float*)d_in[9];
    const float* n2  = (const float*)d_in[10];
    const float* n3  = (const float*)d_in[11];
    const float* n4  = (const float*)d_in[12];
    const float* qn  = (const float*)d_in[13];
    const float* kn  = (const float*)d_in[14];
    const float* nf  = (const float*)d_in[15];
    const float* cosb = (const float*)d_in[16];
    const float* sinb = (const float*)d_in[17];
    float* out = (float*)d_out;

    float *x, *q, *k, *v, *t, *f1, *f2;
    cudaGetSymbolAddress((void**)&x,  g_x);
    cudaGetSymbolAddress((void**)&q,  g_q);
    cudaGetSymbolAddress((void**)&k,  g_k);
    cudaGetSymbolAddress((void**)&v,  g_v);
    cudaGetSymbolAddress((void**)&t,  g_t);
    cudaGetSymbolAddress((void**)&f1, g_f1);
    cudaGetSymbolAddress((void**)&f2, g_f2);

    __nv_bfloat16 *ah, *al, *wqh, *wql, *wkh, *wkl, *wvh, *wvl, *woh, *wol,
                  *w1h, *w1l, *w2h, *w2l, *w3h, *w3l, *eh, *el;
    cudaGetSymbolAddress((void**)&ah,  g_a_h);   cudaGetSymbolAddress((void**)&al,  g_a_l);
    cudaGetSymbolAddress((void**)&wqh, g_wqt_h); cudaGetSymbolAddress((void**)&wql, g_wqt_l);
    cudaGetSymbolAddress((void**)&wkh, g_wkt_h); cudaGetSymbolAddress((void**)&wkl, g_wkt_l);
    cudaGetSymbolAddress((void**)&wvh, g_wvt_h); cudaGetSymbolAddress((void**)&wvl, g_wvt_l);
    cudaGetSymbolAddress((void**)&woh, g_wot_h); cudaGetSymbolAddress((void**)&wol, g_wot_l);
    cudaGetSymbolAddress((void**)&w1h, g_w1t_h); cudaGetSymbolAddress((void**)&w1l, g_w1t_l);
    cudaGetSymbolAddress((void**)&w2h, g_w2t_h); cudaGetSymbolAddress((void**)&w2l, g_w2t_l);
    cudaGetSymbolAddress((void**)&w3h, g_w3t_h); cudaGetSymbolAddress((void**)&w3l, g_w3t_l);
    cudaGetSymbolAddress((void**)&eh,  g_emb_h); cudaGetSymbolAddress((void**)&el,  g_emb_l);

    cudaFuncSetAttribute(gemm_bf16, cudaFuncAttributeMaxDynamicSharedMemorySize, GSMEM);

    // weight conversion (transpose + split)
    dim3 wb(32, 8);
    wconv_kernel<<<dim3(1024/32, 1024/32, NL), wb>>>(Wq, wqh, wql, 1024, 1024);
    wconv_kernel<<<dim3(256/32,  1024/32, NL), wb>>>(Wk, wkh, wkl, 1024, 256);
    wconv_kernel<<<dim3(256/32,  1024/32, NL), wb>>>(Wv, wvh, wvl, 1024, 256);
    wconv_kernel<<<dim3(1024/32, 1024/32, NL), wb>>>(Wo, woh, wol, 1024, 1024);
    wconv_kernel<<<dim3(4096/32, 1024/32, NL), wb>>>(W1, w1h, w1l, 1024, 4096);
    wconv_kernel<<<dim3(4096/32, 1024/32, NL), wb>>>(W2, w2h, w2l, 1024, 4096);
    wconv_kernel<<<dim3(1024/32, 4096/32, NL), wb>>>(W3, w3h, w3l, 4096, 1024);
    split_kernel<<<(VOCAB*DIM)/256, 256>>>(emb, eh, el, VOCAB*DIM);

    embed_kernel<<<NTOK, 256>>>(ids, emb, x);

    const int MT = NTOK / 128;   // 32 M tiles

    for (int l = 0; l < NL; l++) {
        const int window = (l < NL - 4) ? WIN : 0;

        rmsnorm_split_kernel<<<NTOK, 256>>>(x, n1 + (size_t)l * DIM, ah, al);

        gemm_bf16<<<dim3(MT, 1024/128), 256, GSMEM>>>(ah, al,
            wqh + (size_t)l*1024*1024, wql + (size_t)l*1024*1024, q, 1024, 1024);
        gemm_bf16<<<dim3(MT, 256/128), 256, GSMEM>>>(ah, al,
            wkh + (size_t)l*256*1024, wkl + (size_t)l*256*1024, k, 256, 1024);
        gemm_bf16<<<dim3(MT, 256/128), 256, GSMEM>>>(ah, al,
            wvh + (size_t)l*256*1024, wvl + (size_t)l*256*1024, v, 256, 1024);

        qkrope_kernel<<<dim3(NTOK, NH), 64>>>(q, qn + (size_t)l * HDIM, cosb, sinb, NH);
        qkrope_kernel<<<dim3(NTOK, NG), 64>>>(k, kn + (size_t)l * HDIM, cosb, sinb, NG);

        attn_kernel<<<dim3(SEQ, BATCH, NH), 128>>>(q, k, v, ah, al, window);

        gemm_bf16<<<dim3(MT, 1024/128), 256, GSMEM>>>(ah, al,
            woh + (size_t)l*1024*1024, wol + (size_t)l*1024*1024, t, 1024, 1024);
        addrms_kernel<<<NTOK, 256>>>(x, t, n2 + (size_t)l * DIM);

        rmsnorm_split_kernel<<<NTOK, 256>>>(x, n3 + (size_t)l * DIM, ah, al);
        gemm_bf16<<<dim3(MT, 4096/128), 256, GSMEM>>>(ah, al,
            w1h + (size_t)l*4096*1024, w1l + (size_t)l*4096*1024, f1, 4096, 1024);
        gemm_bf16<<<dim3(MT, 4096/128), 256, GSMEM>>>(ah, al,
            w2h + (size_t)l*4096*1024, w2l + (size_t)l*4096*1024, f2, 4096, 1024);
        silu_split_kernel<<<(NTOK*FF)/256, 256>>>(f1, f2, ah, al, NTOK*FF);
        gemm_bf16<<<dim3(MT, 1024/128), 256, GSMEM>>>(ah, al,
            w3h + (size_t)l*1024*4096, w3l + (size_t)l*1024*4096, t, 1024, 4096);
        addrms_kernel<<<NTOK, 256>>>(x, t, n4 + (size_t)l * DIM);
    }

    rmsnorm_split_kernel<<<NTOK, 256>>>(x, nf, ah, al);
    gemm_bf16<<<dim3(MT, VOCAB/128), 256, GSMEM>>>(ah, al, eh, el, out, VOCAB, 1024);
}

// round 4
// speedup vs baseline: 2.8958x; 1.8792x over previous
#include <cuda_runtime.h>
#include <cuda_bf16.h>
#include <math.h>
#include <stdint.h>

#define BATCH  2
#define SEQ    2048
#define DIM    1024
#define NH     16
#define NG     4
#define GRP    4
#define HDIM   64
#define FF     4096
#define NL     8
#define VOCAB  32000
#define WIN    1024
#define EPS    1e-6f
#define NTOK   (BATCH*SEQ)   // 4096
#define QKVW   1536          // packed qkv row width
#define F2W    8192          // packed w1|w2 width

// ======================= scratch =======================
__device__ float g_x   [NTOK*DIM];
__device__ float g_qkv [NTOK*QKVW];
__device__ float g_t   [NTOK*DIM];
__device__ float g_f12 [NTOK*F2W];

__device__ __align__(128) __nv_bfloat16 g_a_h[NTOK*FF];
__device__ __align__(128) __nv_bfloat16 g_a_l[NTOK*FF];
__device__ __align__(128) __nv_bfloat16 g_wqkv_h[NL*QKVW*1024];
__device__ __align__(128) __nv_bfloat16 g_wqkv_l[NL*QKVW*1024];
__device__ __align__(128) __nv_bfloat16 g_wot_h[NL*1024*1024];
__device__ __align__(128) __nv_bfloat16 g_wot_l[NL*1024*1024];
__device__ __align__(128) __nv_bfloat16 g_w12_h[NL*F2W*1024];
__device__ __align__(128) __nv_bfloat16 g_w12_l[NL*F2W*1024];
__device__ __align__(128) __nv_bfloat16 g_w3t_h[NL*1024*4096];
__device__ __align__(128) __nv_bfloat16 g_w3t_l[NL*1024*4096];
__device__ __align__(128) __nv_bfloat16 g_emb_h[VOCAB*DIM];
__device__ __align__(128) __nv_bfloat16 g_emb_l[VOCAB*DIM];

// ======================= small kernels =======================
__global__ void embed_kernel(const int* __restrict__ ids,
                             const float* __restrict__ emb,
                             float* __restrict__ x) {
    int t = blockIdx.x;
    int id = ids[t];
    const float* e = emb + (size_t)id * DIM;
    float* xp = x + (size_t)t * DIM;
    for (int d = threadIdx.x; d < DIM; d += blockDim.x)
        xp[d] = e[d] * 32.0f;
}

__global__ void split_kernel(const float* __restrict__ in,
                             __nv_bfloat16* __restrict__ oh,
                             __nv_bfloat16* __restrict__ ol, int n) {
    int i = blockIdx.x * 256 + threadIdx.x;
    if (i < n) {
        float v = in[i];
        __nv_bfloat16 h = __float2bfloat16(v);
        oh[i] = h;
        ol[i] = __float2bfloat16(v - __bfloat162float(h));
    }
}

// transpose + split into packed buffer: W [L,K,N] fp32 -> out [L, rowoff+N, K]
__global__ void wconv_kernel(const float* __restrict__ W,
                             __nv_bfloat16* __restrict__ oh,
                             __nv_bfloat16* __restrict__ ol,
                             int K, int N, size_t lstride, int rowoff) {
    __shared__ float t[32][33];
    int l = blockIdx.z;
    const float* Wl = W + (size_t)l * K * N;
    size_t ob = (size_t)l * lstride;
    int n0 = blockIdx.x * 32, k0 = blockIdx.y * 32;
    int tx = threadIdx.x, ty = threadIdx.y;
#pragma unroll
    for (int r = 0; r < 32; r += 8)
        t[ty + r][tx] = Wl[(size_t)(k0 + ty + r) * N + n0 + tx];
    __syncthreads();
#pragma unroll
    for (int r = 0; r < 32; r += 8) {
        float v = t[tx][ty + r];
        __nv_bfloat16 h = __float2bfloat16(v);
        size_t o = ob + (size_t)(rowoff + n0 + ty + r) * K + k0 + tx;
        oh[o] = h;
        ol[o] = __float2bfloat16(v - __bfloat162float(h));
    }
}

__global__ __launch_bounds__(256) void rmsnorm_split_kernel(const float* __restrict__ in,
                                                            const float* __restrict__ scale,
                                                            __nv_bfloat16* __restrict__ oh,
                                                            __nv_bfloat16* __restrict__ ol) {
    const int t = blockIdx.x;
    const float* xp = in + (size_t)t * DIM;
    float ss = 0.f;
    for (int d = threadIdx.x; d < DIM; d += 256) { float v = xp[d]; ss += v * v; }
    __shared__ float red[256];
    red[threadIdx.x] = ss; __syncthreads();
    for (int o = 128; o > 0; o >>= 1) {
        if (threadIdx.x < o) red[threadIdx.x] += red[threadIdx.x + o];
        __syncthreads();
    }
    const float r = rsqrtf(red[0] * (1.0f / DIM) + EPS);
    for (int d = threadIdx.x; d < DIM; d += 256) {
        float v = xp[d] * r * (1.0f + scale[d]);
        __nv_bfloat16 h = __float2bfloat16(v);
        oh[(size_t)t * DIM + d] = h;
        ol[(size_t)t * DIM + d] = __float2bfloat16(v - __bfloat162float(h));
    }
}

__global__ __launch_bounds__(256) void addrms_kernel(float* __restrict__ x,
                                                     const float* __restrict__ tin,
                                                     const float* __restrict__ scale) {
    const int t = blockIdx.x;
    const float* tp = tin + (size_t)t * DIM;
    float ss = 0.f;
    for (int d = threadIdx.x; d < DIM; d += 256) { float v = tp[d]; ss += v * v; }
    __shared__ float red[256];
    red[threadIdx.x] = ss; __syncthreads();
    for (int o = 128; o > 0; o >>= 1) {
        if (threadIdx.x < o) red[threadIdx.x] += red[threadIdx.x + o];
        __syncthreads();
    }
    const float r = rsqrtf(red[0] * (1.0f / DIM) + EPS);
    float* xp = x + (size_t)t * DIM;
    for (int d = threadIdx.x; d < 256 * 4; d += 256)
        xp[d] += tp[d] * r * (1.0f + scale[d]);
}

// per-head rmsnorm + rope, strided (packed qkv buffer)
__global__ __launch_bounds__(64) void qkrope_kernel(float* __restrict__ x,
                                                    const float* __restrict__ scale,
                                                    const float* __restrict__ cosb,
                                                    const float* __restrict__ sinb,
                                                    int headoff) {
    const int token = blockIdx.x;
    const int h = blockIdx.y;
    const int pos = token % SEQ;
    const int d = threadIdx.x;
    float* xp = x + (size_t)token * QKVW + headoff + h * HDIM;
    const float val = xp[d];
    __shared__ float sh[HDIM];
    sh[d] = val * val;
    __syncthreads();
    for (int o = 32; o > 0; o >>= 1) {
        if (d < o) sh[d] += sh[d + o];
        __syncthreads();
    }
    const float r = rsqrtf(sh[0] * (1.0f / HDIM) + EPS);
    __syncthreads();
    const float nv = val * r * (1.0f + scale[d]);
    sh[d] = nv;
    __syncthreads();
    const float rot = (d < 32) ? -sh[d + 32] : sh[d - 32];
    xp[d] = nv * cosb[pos * HDIM + d] + rot * sinb[pos * HDIM + d];
}

// ======================= flash attention (fp32, 64q x 64k tiles) =======================
#define APAD 68
#define FA_SMEM ((3*64*APAD + 64*65 + 3*64) * 4)

__global__ __launch_bounds__(256, 3) void flash_attn(const float* __restrict__ qkv,
                                                     __nv_bfloat16* __restrict__ oh,
                                                     __nv_bfloat16* __restrict__ ol,
                                                     int window) {
    extern __shared__ float sm[];
    float* qs    = sm;                  // [64][68]
    float* ks    = qs + 64 * APAD;      // [64][68]
    float* vs    = ks + 64 * APAD;      // [64][68]
    float* sc    = vs + 64 * APAD;      // [64][65]
    float* mrun  = sc + 64 * 65;        // [64]
    float* srun  = mrun + 64;           // [64]
    float* alpha = srun + 64;           // [64]

    const int qt = blockIdx.x, b = blockIdx.y, h = blockIdx.z;
    const int g = h / GRP;
    const int tid = threadIdx.x;
    const int q0 = qt * 64;
    const int w = tid >> 5, lane = tid & 31;
    const int av_q = tid >> 2;
    const int av_d = (tid & 3) * 16;

    // load Q tile (scaled)
    for (int i = tid; i < 64 * 16; i += 256) {
        int r = i >> 4, c4 = (i & 15) << 2;
        float4 v4 = *(const float4*)(qkv + (size_t)(b * SEQ + q0 + r) * QKVW + h * HDIM + c4);
        v4.x *= 0.125f; v4.y *= 0.125f; v4.z *= 0.125f; v4.w *= 0.125f;
        *(float4*)&qs[r * APAD + c4] = v4;
    }
    if (tid < 64) { mrun[tid] = -1e30f; srun[tid] = 0.f; }
    float out[16] = {};

    int t0 = 0;
    if (window > 0) { int lo = q0 - window; if (lo > 0) t0 = lo >> 6; }

    for (int kt = t0; kt <= qt; kt++) {
        __syncthreads();   // previous AV reads done before overwriting K/V
        const int k0 = kt * 64;
        for (int i = tid; i < 64 * 16; i += 256) {
            int r = i >> 4, c4 = (i & 15) << 2;
            size_t base = (size_t)(b * SEQ + k0 + r) * QKVW + g * HDIM + c4;
            *(float4*)&ks[r * APAD + c4] = *(const float4*)(qkv + base + 1024);
            *(float4*)&vs[r * APAD + c4] = *(const float4*)(qkv + base + 1280);
        }
        __syncthreads();

        // scores: warp w -> queries q0+w*8..+8; lane -> keys lane, lane+32
        float s1[8], s2[8];
#pragma unroll
        for (int i = 0; i < 8; i++) { s1[i] = 0.f; s2[i] = 0.f; }
#pragma unroll 4
        for (int d4 = 0; d4 < 16; d4++) {
            float4 k1 = *(float4*)&ks[lane * APAD + d4 * 4];
            float4 k2 = *(float4*)&ks[(lane + 32) * APAD + d4 * 4];
#pragma unroll
            for (int qq = 0; qq < 8; qq++) {
                float4 qv = *(float4*)&qs[(w * 8 + qq) * APAD + d4 * 4];
                s1[qq] += qv.x * k1.x + qv.y * k1.y + qv.z * k1.z + qv.w * k1.w;
                s2[qq] += qv.x * k2.x + qv.y * k2.y + qv.z * k2.z + qv.w * k2.w;
            }
        }
        const int j1 = k0 + lane, j2 = k0 + lane + 32;
#pragma unroll
        for (int qq = 0; qq < 8; qq++) {
            const int ql = w * 8 + qq;
            const int qi = q0 + ql;
            bool v1 = (j1 <= qi) && (window == 0 || qi - j1 <= window);
            bool v2 = (j2 <= qi) && (window == 0 || qi - j2 <= window);
            float a = v1 ? s1[qq] : -1e30f;
            float c = v2 ? s2[qq] : -1e30f;
            float mx = fmaxf(a, c);
#pragma unroll
            for (int o = 16; o > 0; o >>= 1)
                mx = fmaxf(mx, __shfl_xor_sync(0xffffffffu, mx, o));
            const float mold = mrun[ql];
            const float mnew = fmaxf(mold, mx);
            float p1 = v1 ? __expf(a - mnew) : 0.f;
            float p2 = v2 ? __expf(c - mnew) : 0.f;
            float ps = p1 + p2;
#pragma unroll
            for (int o = 16; o > 0; o >>= 1)
                ps += __shfl_xor_sync(0xffffffffu, ps, o);
            if (lane == 0) {
                const float al_ = __expf(mold - mnew);
                mrun[ql] = mnew;
                srun[ql] = srun[ql] * al_ + ps;
                alpha[ql] = al_;
            }
            sc[ql * 65 + lane]      = p1;
            sc[ql * 65 + lane + 32] = p2;
        }
        __syncthreads();

        // AV: thread -> query av_q, dims av_d..av_d+16
        const float al_ = alpha[av_q];
#pragma unroll
        for (int i = 0; i < 16; i++) out[i] *= al_;
        for (int kk = 0; kk < 64; kk++) {
            const float wgt = sc[av_q * 65 + kk];
            const float* vp = &vs[kk * APAD + av_d];
#pragma unroll
            for (int i = 0; i < 16; i += 4) {
                float4 v4 = *(const float4*)(vp + i);
                out[i]     += wgt * v4.x;
                out[i + 1] += wgt * v4.y;
                out[i + 2] += wgt * v4.z;
                out[i + 3] += wgt * v4.w;
            }
        }
    }
    __syncthreads();
    const float inv = 1.0f / srun[av_q];
    size_t obase = (size_t)(b * SEQ + q0 + av_q) * (NH * HDIM) + h * HDIM + av_d;
#pragma unroll
    for (int i = 0; i < 16; i++) {
        float o = out[i] * inv;
        __nv_bfloat16 hv = __float2bfloat16(o);
        oh[obase + i] = hv;
        ol[obase + i] = __float2bfloat16(o - __bfloat162float(hv));
    }
}

// silu(f12[:, :4096]) * f12[:, 4096:] -> split bf16
__global__ void silu_split_kernel(const float* __restrict__ f12,
                                  __nv_bfloat16* __restrict__ oh,
                                  __nv_bfloat16* __restrict__ ol) {
    int i = blockIdx.x * 256 + threadIdx.x;
    int t = i >> 12, d = i & 4095;
    float v = f12[(size_t)t * F2W + d];
    float s = v / (1.0f + __expf(-v)) * f12[(size_t)t * F2W + 4096 + d];
    __nv_bfloat16 h = __float2bfloat16(s);
    oh[i] = h;
    ol[i] = __float2bfloat16(s - __bfloat162float(h));
}

// ======================= mma.sync bf16 GEMM =======================
#define SSTG      32768
#define GSMEM     (3*SSTG)

__device__ __forceinline__ uint32_t smem_u32(const void* p) {
    uint32_t a;
    asm("{ .reg .u64 t; cvta.to.shared.u64 t, %1; cvt.u32.u64 %0, t; }" : "=r"(a) : "l"(p));
    return a;
}
__device__ __forceinline__ void cp16(uint32_t s, const void* g) {
    asm volatile("cp.async.cg.shared.global [%0], [%1], 16;" :: "r"(s), "l"(g));
}
#define LDMX4(r0, r1, r2, r3, addr) \
    asm volatile("ldmatrix.sync.aligned.m8n8.x4.shared.b16 {%0,%1,%2,%3}, [%4];" \
        : "=r"(r0), "=r"(r1), "=r"(r2), "=r"(r3) : "r"(addr))
#define MMA16816(d, a, b) \
    asm volatile("mma.sync.aligned.m16n8k16.row.col.f32.bf16.bf16.f32 " \
        "{%0,%1,%2,%3}, {%4,%5,%6,%7}, {%8,%9}, {%0,%1,%2,%3};" \
        : "+f"((d)[0]), "+f"((d)[1]), "+f"((d)[2]), "+f"((d)[3]) \
        : "r"((a)[0]), "r"((a)[1]), "r"((a)[2]), "r"((a)[3]), "r"((b)[0]), "r"((b)[1]))

__device__ __forceinline__ void stage_load(uint32_t st,
                                           const __nv_bfloat16* Ah, const __nv_bfloat16* Al,
                                           const __nv_bfloat16* Bh, const __nv_bfloat16* Bl,
                                           int m0, int n0, int k0, int K, int tid) {
#pragma unroll
    for (int c = tid; c < 512; c += 256) {
        int r = c >> 2, u = c & 3;
        uint32_t off = r * 64 + ((u ^ ((r >> 1) & 3)) << 4);
        size_t ga = (size_t)(m0 + r) * K + k0 + u * 8;
        size_t gb = (size_t)(n0 + r) * K + k0 + u * 8;
        cp16(st + off,          Ah + ga);
        cp16(st + 8192  + off,  Al + ga);
        cp16(st + 16384 + off,  Bh + gb);
        cp16(st + 24576 + off,  Bl + gb);
    }
    asm volatile("cp.async.commit_group;" ::: "memory");
}

__global__ __launch_bounds__(256, 1) void gemm_bf16(
    const __nv_bfloat16* __restrict__ Ah, const __nv_bfloat16* __restrict__ Al,
    const __nv_bfloat16* __restrict__ Bh, const __nv_bfloat16* __restrict__ Bl,
    float* __restrict__ C, int N, int K)
{
    extern __shared__ __align__(128) char smem[];
    const uint32_t sb = smem_u32(smem);
    const int tid = threadIdx.x;
    const int lane = tid & 31;
    const int w = tid >> 5;
    const int wm = w & 3;
    const int wn = w >> 2;
    const int m0 = blockIdx.x * 128;
    const int n0 = blockIdx.y * 128;
    const int niter = K >> 5;

    float acc[2][8][4] = {};

    stage_load(sb,        Ah, Al, Bh, Bl, m0, n0, 0,  K, tid);
    stage_load(sb + SSTG, Ah, Al, Bh, Bl, m0, n0, 32, K, tid);

    const int a_r = wm * 32 + (lane & 15);
    const int a_uadd = lane >> 4;
    const int b_mat = lane >> 3;
    const int b_r0 = wn * 64 + ((b_mat >> 1) << 3) + (lane & 7);
    const int b_uadd = b_mat & 1;

    for (int it = 0; it < niter; it++) {
        if (it + 2 < niter) { asm volatile("cp.async.wait_group 1;" ::: "memory"); }
        else                { asm volatile("cp.async.wait_group 0;" ::: "memory"); }
        __syncthreads();
        if (it + 2 < niter)
            stage_load(sb + ((it + 2) % 3) * SSTG, Ah, Al, Bh, Bl, m0, n0, (it + 2) * 32, K, tid);

        const uint32_t st = sb + (it % 3) * SSTG;
#pragma unroll
        for (int ks = 0; ks < 2; ks++) {
            uint32_t ah[2][4], al[2][4], bh[8][2], bl[8][2];
#pragma unroll
            for (int mb = 0; mb < 2; mb++) {
                int r = a_r + mb * 16;
                int u = ks * 2 + a_uadd;
                uint32_t off = r * 64 + ((u ^ ((r >> 1) & 3)) << 4);
                LDMX4(ah[mb][0], ah[mb][1], ah[mb][2], ah[mb][3], st + off);
                LDMX4(al[mb][0], al[mb][1], al[mb][2], al[mb][3], st + 8192 + off);
            }
#pragma unroll
            for (int qd = 0; qd < 4; qd++) {
                int r = b_r0 + qd * 16;
                int u = ks * 2 + b_uadd;
                uint32_t off = r * 64 + ((u ^ ((r >> 1) & 3)) << 4);
                uint32_t t0, t1, t2, t3;
                LDMX4(t0, t1, t2, t3, st + 16384 + off);
                bh[2*qd][0] = t0; bh[2*qd][1] = t1; bh[2*qd+1][0] = t2; bh[2*qd+1][1] = t3;
                LDMX4(t0, t1, t2, t3, st + 24576 + off);
                bl[2*qd][0] = t0; bl[2*qd][1] = t1; bl[2*qd+1][0] = t2; bl[2*qd+1][1] = t3;
            }
#pragma unroll
            for (int mb = 0; mb < 2; mb++)
#pragma unroll
                for (int nb = 0; nb < 8; nb++) {
                    MMA16816(acc[mb][nb], ah[mb], bh[nb]);
                    MMA16816(acc[mb][nb], al[mb], bh[nb]);
                    MMA16816(acc[mb][nb], ah[mb], bl[nb]);
                }
        }
    }

#pragma unroll
    for (int mb = 0; mb < 2; mb++) {
        int row = m0 + wm * 32 + mb * 16 + (lane >> 2);
#pragma unroll
        for (int nb = 0; nb < 8; nb++) {
            int col = n0 + wn * 64 + nb * 8 + 2 * (lane & 3);
            *(float2*)(C + (size_t)row * N + col)       = make_float2(acc[mb][nb][0], acc[mb][nb][1]);
            *(float2*)(C + (size_t)(row + 8) * N + col) = make_float2(acc[mb][nb][2], acc[mb][nb][3]);
        }
    }
}

// ======================= host driver =======================
extern "C" void kernel_launch(void* const* d_in, const int* in_sizes, int n_in,
                              void* d_out, int out_size) {
    const int*   ids = (const int*)  d_in[0];
    const float* emb = (const float*)d_in[1];
    const float* Wq  = (const float*)d_in[2];
    const float* Wk  = (const float*)d_in[3];
    const float* Wv  = (const float*)d_in[4];
    const float* Wo  = (const float*)d_in[5];
    const float* W1  = (const float*)d_in[6];
    const float* W2  = (const float*)d_in[7];
    const float* W3  = (const float*)d_in[8];
    const float* n1  = (const float*)d_in[9];
    const float* n2  = (const float*)d_in[10];
    const float* n3  = (const float*)d_in[11];
    const float* n4  = (const float*)d_in[12];
    const float* qn  = (const float*)d_in[13];
    const float* kn  = (const float*)d_in[14];
    const float* nf  = (const float*)d_in[15];
    const float* cosb = (const float*)d_in[16];
    const float* sinb = (const float*)d_in[17];
    float* out = (float*)d_out;

    float *x, *qkv, *t, *f12;
    cudaGetSymbolAddress((void**)&x,   g_x);
    cudaGetSymbolAddress((void**)&qkv, g_qkv);
    cudaGetSymbolAddress((void**)&t,   g_t);
    cudaGetSymbolAddress((void**)&f12, g_f12);

    __nv_bfloat16 *ah, *al, *wqkvh, *wqkvl, *woh, *wol, *w12h, *w12l, *w3h, *w3l, *eh, *el;
    cudaGetSymbolAddress((void**)&ah,    g_a_h);    cudaGetSymbolAddress((void**)&al,    g_a_l);
    cudaGetSymbolAddress((void**)&wqkvh, g_wqkv_h); cudaGetSymbolAddress((void**)&wqkvl, g_wqkv_l);
    cudaGetSymbolAddress((void**)&woh,   g_wot_h);  cudaGetSymbolAddress((void**)&wol,   g_wot_l);
    cudaGetSymbolAddress((void**)&w12h,  g_w12_h);  cudaGetSymbolAddress((void**)&w12l,  g_w12_l);
    cudaGetSymbolAddress((void**)&w3h,   g_w3t_h);  cudaGetSymbolAddress((void**)&w3l,   g_w3t_l);
    cudaGetSymbolAddress((void**)&eh,    g_emb_h);  cudaGetSymbolAddress((void**)&el,    g_emb_l);

    cudaFuncSetAttribute(gemm_bf16, cudaFuncAttributeMaxDynamicSharedMemorySize, GSMEM);
    cudaFuncSetAttribute(flash_attn, cudaFuncAttributeMaxDynamicSharedMemorySize, FA_SMEM);

    // weight conversion (transpose + split into packed layouts)
    dim3 wb(32, 8);
    wconv_kernel<<<dim3(1024/32, 1024/32, NL), wb>>>(Wq, wqkvh, wqkvl, 1024, 1024, (size_t)QKVW*1024, 0);
    wconv_kernel<<<dim3(256/32,  1024/32, NL), wb>>>(Wk, wqkvh, wqkvl, 1024, 256,  (size_t)QKVW*1024, 1024);
    wconv_kernel<<<dim3(256/32,  1024/32, NL), wb>>>(Wv, wqkvh, wqkvl, 1024, 256,  (size_t)QKVW*1024, 1280);
    wconv_kernel<<<dim3(1024/32, 1024/32, NL), wb>>>(Wo, woh, wol, 1024, 1024, (size_t)1024*1024, 0);
    wconv_kernel<<<dim3(4096/32, 1024/32, NL), wb>>>(W1, w12h, w12l, 1024, 4096, (size_t)F2W*1024, 0);
    wconv_kernel<<<dim3(4096/32, 1024/32, NL), wb>>>(W2, w12h, w12l, 1024, 4096, (size_t)F2W*1024, 4096);
    wconv_kernel<<<dim3(1024/32, 4096/32, NL), wb>>>(W3, w3h, w3l, 4096, 1024, (size_t)4096*1024, 0);
    split_kernel<<<(VOCAB*DIM)/256, 256>>>(emb, eh, el, VOCAB*DIM);

    embed_kernel<<<NTOK, 256>>>(ids, emb, x);

    const int MT = NTOK / 128;   // 32

    for (int l = 0; l < NL; l++) {
        const int window = (l < NL - 4) ? WIN : 0;

        rmsnorm_split_kernel<<<NTOK, 256>>>(x, n1 + (size_t)l * DIM, ah, al);

        gemm_bf16<<<dim3(MT, QKVW/128), 256, GSMEM>>>(ah, al,
            wqkvh + (size_t)l*QKVW*1024, wqkvl + (size_t)l*QKVW*1024, qkv, QKVW, 1024);

        qkrope_kernel<<<dim3(NTOK, NH), 64>>>(qkv, qn + (size_t)l * HDIM, cosb, sinb, 0);
        qkrope_kernel<<<dim3(NTOK, NG), 64>>>(qkv, kn + (size_t)l * HDIM, cosb, sinb, 1024);

        flash_attn<<<dim3(SEQ/64, BATCH, NH), 256, FA_SMEM>>>(qkv, ah, al, window);

        gemm_bf16<<<dim3(MT, 1024/128), 256, GSMEM>>>(ah, al,
            woh + (size_t)l*1024*1024, wol + (size_t)l*1024*1024, t, 1024, 1024);
        addrms_kernel<<<NTOK, 256>>>(x, t, n2 + (size_t)l * DIM);

        rmsnorm_split_kernel<<<NTOK, 256>>>(x, n3 + (size_t)l * DIM, ah, al);
        gemm_bf16<<<dim3(MT, F2W/128), 256, GSMEM>>>(ah, al,
            w12h + (size_t)l*F2W*1024, w12l + (size_t)l*F2W*1024, f12, F2W, 1024);
        silu_split_kernel<<<(NTOK*FF)/256, 256>>>(f12, ah, al);
        gemm_bf16<<<dim3(MT, 1024/128), 256, GSMEM>>>(ah, al,
            w3h + (size_t)l*1024*4096, w3l + (size_t)l*1024*4096, t, 1024, 4096);
        addrms_kernel<<<NTOK, 256>>>(x, t, n4 + (size_t)l * DIM);
    }

    rmsnorm_split_kernel<<<NTOK, 256>>>(x, nf, ah, al);
    gemm_bf16<<<dim3(MT, VOCAB/128), 256, GSMEM>>>(ah, al, eh, el, out, VOCAB, 1024);
}

// round 5
// speedup vs baseline: 3.5413x; 1.2229x over previous
#include <cuda_runtime.h>
#include <cuda_fp16.h>
#include <math.h>
#include <stdint.h>

#define BATCH  2
#define SEQ    2048
#define DIM    1024
#define NH     16
#define NG     4
#define GRP    4
#define HDIM   64
#define FF     4096
#define NL     8
#define VOCAB  32000
#define WIN    1024
#define EPS    1e-6f
#define NTOK   (BATCH*SEQ)   // 4096
#define QKVW   1536          // packed qkv row width
#define F2W    8192          // packed w1|w2 width

// ======================= scratch =======================
__device__ float g_x   [NTOK*DIM];
__device__ float g_qkv [NTOK*QKVW];
__device__ float g_t   [NTOK*DIM];
__device__ float g_f12 [NTOK*F2W];

__device__ __align__(128) __half g_a_h[NTOK*FF];
__device__ __align__(128) __half g_a_l[NTOK*FF];
__device__ __align__(128) __half g_wqkv[NL*QKVW*1024];
__device__ __align__(128) __half g_wot [NL*1024*1024];
__device__ __align__(128) __half g_w12 [NL*F2W*1024];
__device__ __align__(128) __half g_w3t [NL*1024*4096];
__device__ __align__(128) __half g_emb [VOCAB*DIM];

// ======================= small kernels =======================
__global__ void embed_kernel(const int* __restrict__ ids,
                             const float* __restrict__ emb,
                             float* __restrict__ x) {
    int t = blockIdx.x;
    int id = ids[t];
    const float* e = emb + (size_t)id * DIM;
    float* xp = x + (size_t)t * DIM;
    for (int d = threadIdx.x; d < DIM; d += blockDim.x)
        xp[d] = e[d] * 32.0f;
}

// fp32 -> fp16 (no split; for weights/embedding B operand)
__global__ void half_kernel(const float* __restrict__ in,
                            __half* __restrict__ o, int n) {
    int i = blockIdx.x * 256 + threadIdx.x;
    if (i < n) o[i] = __float2half(in[i]);
}

// transpose to fp16 packed: W [L,K,N] fp32 -> out [L, rowoff+N, K]
__global__ void wconv_kernel(const float* __restrict__ W,
                             __half* __restrict__ o,
                             int K, int N, size_t lstride, int rowoff) {
    __shared__ float t[32][33];
    int l = blockIdx.z;
    const float* Wl = W + (size_t)l * K * N;
    size_t ob = (size_t)l * lstride;
    int n0 = blockIdx.x * 32, k0 = blockIdx.y * 32;
    int tx = threadIdx.x, ty = threadIdx.y;
#pragma unroll
    for (int r = 0; r < 32; r += 8)
        t[ty + r][tx] = Wl[(size_t)(k0 + ty + r) * N + n0 + tx];
    __syncthreads();
#pragma unroll
    for (int r = 0; r < 32; r += 8)
        o[ob + (size_t)(rowoff + n0 + ty + r) * K + k0 + tx] = __float2half(t[tx][ty + r]);
}

__global__ __launch_bounds__(256) void rmsnorm_split_kernel(const float* __restrict__ in,
                                                            const float* __restrict__ scale,
                                                            __half* __restrict__ oh,
                                                            __half* __restrict__ ol) {
    const int t = blockIdx.x;
    const float* xp = in + (size_t)t * DIM;
    float ss = 0.f;
    for (int d = threadIdx.x; d < DIM; d += 256) { float v = xp[d]; ss += v * v; }
    __shared__ float red[256];
    red[threadIdx.x] = ss; __syncthreads();
    for (int o = 128; o > 0; o >>= 1) {
        if (threadIdx.x < o) red[threadIdx.x] += red[threadIdx.x + o];
        __syncthreads();
    }
    const float r = rsqrtf(red[0] * (1.0f / DIM) + EPS);
    for (int d = threadIdx.x; d < DIM; d += 256) {
        float v = xp[d] * r * (1.0f + scale[d]);
        __half h = __float2half(v);
        oh[(size_t)t * DIM + d] = h;
        ol[(size_t)t * DIM + d] = __float2half(v - __half2float(h));
    }
}

__global__ __launch_bounds__(256) void addrms_kernel(float* __restrict__ x,
                                                     const float* __restrict__ tin,
                                                     const float* __restrict__ scale) {
    const int t = blockIdx.x;
    const float* tp = tin + (size_t)t * DIM;
    float ss = 0.f;
    for (int d = threadIdx.x; d < DIM; d += 256) { float v = tp[d]; ss += v * v; }
    __shared__ float red[256];
    red[threadIdx.x] = ss; __syncthreads();
    for (int o = 128; o > 0; o >>= 1) {
        if (threadIdx.x < o) red[threadIdx.x] += red[threadIdx.x + o];
        __syncthreads();
    }
    const float r = rsqrtf(red[0] * (1.0f / DIM) + EPS);
    float* xp = x + (size_t)t * DIM;
    for (int d = threadIdx.x; d < DIM; d += 256)
        xp[d] += tp[d] * r * (1.0f + scale[d]);
}

// per-head rmsnorm + rope, strided (packed qkv buffer)
__global__ __launch_bounds__(64) void qkrope_kernel(float* __restrict__ x,
                                                    const float* __restrict__ scale,
                                                    const float* __restrict__ cosb,
                                                    const float* __restrict__ sinb,
                                                    int headoff) {
    const int token = blockIdx.x;
    const int h = blockIdx.y;
    const int pos = token % SEQ;
    const int d = threadIdx.x;
    float* xp = x + (size_t)token * QKVW + headoff + h * HDIM;
    const float val = xp[d];
    __shared__ float sh[HDIM];
    sh[d] = val * val;
    __syncthreads();
    for (int o = 32; o > 0; o >>= 1) {
        if (d < o) sh[d] += sh[d + o];
        __syncthreads();
    }
    const float r = rsqrtf(sh[0] * (1.0f / HDIM) + EPS);
    __syncthreads();
    const float nv = val * r * (1.0f + scale[d]);
    sh[d] = nv;
    __syncthreads();
    const float rot = (d < 32) ? -sh[d + 32] : sh[d - 32];
    xp[d] = nv * cosb[pos * HDIM + d] + rot * sinb[pos * HDIM + d];
}

// ======================= flash attention (fp32, 64q x 64k tiles) =======================
#define APAD 68
#define FA_SMEM ((3*64*APAD + 64*65 + 3*64) * 4)

__global__ __launch_bounds__(256, 3) void flash_attn(const float* __restrict__ qkv,
                                                     __half* __restrict__ oh,
                                                     __half* __restrict__ ol,
                                                     int window) {
    extern __shared__ float sm[];
    float* qs    = sm;
    float* ks    = qs + 64 * APAD;
    float* vs    = ks + 64 * APAD;
    float* sc    = vs + 64 * APAD;
    float* mrun  = sc + 64 * 65;
    float* srun  = mrun + 64;
    float* alpha = srun + 64;

    const int qt = blockIdx.x, b = blockIdx.y, h = blockIdx.z;
    const int g = h / GRP;
    const int tid = threadIdx.x;
    const int q0 = qt * 64;
    const int w = tid >> 5, lane = tid & 31;
    const int av_q = tid >> 2;
    const int av_d = (tid & 3) * 16;

    for (int i = tid; i < 64 * 16; i += 256) {
        int r = i >> 4, c4 = (i & 15) << 2;
        float4 v4 = *(const float4*)(qkv + (size_t)(b * SEQ + q0 + r) * QKVW + h * HDIM + c4);
        v4.x *= 0.125f; v4.y *= 0.125f; v4.z *= 0.125f; v4.w *= 0.125f;
        *(float4*)&qs[r * APAD + c4] = v4;
    }
    if (tid < 64) { mrun[tid] = -1e30f; srun[tid] = 0.f; }
    float out[16] = {};

    int t0 = 0;
    if (window > 0) { int lo = q0 - window; if (lo > 0) t0 = lo >> 6; }

    for (int kt = t0; kt <= qt; kt++) {
        __syncthreads();
        const int k0 = kt * 64;
        for (int i = tid; i < 64 * 16; i += 256) {
            int r = i >> 4, c4 = (i & 15) << 2;
            size_t base = (size_t)(b * SEQ + k0 + r) * QKVW + g * HDIM + c4;
            *(float4*)&ks[r * APAD + c4] = *(const float4*)(qkv + base + 1024);
            *(float4*)&vs[r * APAD + c4] = *(const float4*)(qkv + base + 1280);
        }
        __syncthreads();

        float s1[8], s2[8];
#pragma unroll
        for (int i = 0; i < 8; i++) { s1[i] = 0.f; s2[i] = 0.f; }
#pragma unroll 4
        for (int d4 = 0; d4 < 16; d4++) {
            float4 k1 = *(float4*)&ks[lane * APAD + d4 * 4];
            float4 k2 = *(float4*)&ks[(lane + 32) * APAD + d4 * 4];
#pragma unroll
            for (int qq = 0; qq < 8; qq++) {
                float4 qv = *(float4*)&qs[(w * 8 + qq) * APAD + d4 * 4];
                s1[qq] += qv.x * k1.x + qv.y * k1.y + qv.z * k1.z + qv.w * k1.w;
                s2[qq] += qv.x * k2.x + qv.y * k2.y + qv.z * k2.z + qv.w * k2.w;
            }
        }
        const int j1 = k0 + lane, j2 = k0 + lane + 32;
#pragma unroll
        for (int qq = 0; qq < 8; qq++) {
            const int ql = w * 8 + qq;
            const int qi = q0 + ql;
            bool v1 = (j1 <= qi) && (window == 0 || qi - j1 <= window);
            bool v2 = (j2 <= qi) && (window == 0 || qi - j2 <= window);
            float a = v1 ? s1[qq] : -1e30f;
            float c = v2 ? s2[qq] : -1e30f;
            float mx = fmaxf(a, c);
#pragma unroll
            for (int o = 16; o > 0; o >>= 1)
                mx = fmaxf(mx, __shfl_xor_sync(0xffffffffu, mx, o));
            const float mold = mrun[ql];
            const float mnew = fmaxf(mold, mx);
            float p1 = v1 ? __expf(a - mnew) : 0.f;
            float p2 = v2 ? __expf(c - mnew) : 0.f;
            float ps = p1 + p2;
#pragma unroll
            for (int o = 16; o > 0; o >>= 1)
                ps += __shfl_xor_sync(0xffffffffu, ps, o);
            if (lane == 0) {
                const float al_ = __expf(mold - mnew);
                mrun[ql] = mnew;
                srun[ql] = srun[ql] * al_ + ps;
                alpha[ql] = al_;
            }
            sc[ql * 65 + lane]      = p1;
            sc[ql * 65 + lane + 32] = p2;
        }
        __syncthreads();

        const float al_ = alpha[av_q];
#pragma unroll
        for (int i = 0; i < 16; i++) out[i] *= al_;
        for (int kk = 0; kk < 64; kk++) {
            const float wgt = sc[av_q * 65 + kk];
            const float* vp = &vs[kk * APAD + av_d];
#pragma unroll
            for (int i = 0; i < 16; i += 4) {
                float4 v4 = *(const float4*)(vp + i);
                out[i]     += wgt * v4.x;
                out[i + 1] += wgt * v4.y;
                out[i + 2] += wgt * v4.z;
                out[i + 3] += wgt * v4.w;
            }
        }
    }
    __syncthreads();
    const float inv = 1.0f / srun[av_q];
    size_t obase = (size_t)(b * SEQ + q0 + av_q) * (NH * HDIM) + h * HDIM + av_d;
#pragma unroll
    for (int i = 0; i < 16; i++) {
        float o = out[i] * inv;
        __half hv = __float2half(o);
        oh[obase + i] = hv;
        ol[obase + i] = __float2half(o - __half2float(hv));
    }
}

// silu(f12[:, :4096]) * f12[:, 4096:] -> split fp16
__global__ void silu_split_kernel(const float* __restrict__ f12,
                                  __half* __restrict__ oh,
                                  __half* __restrict__ ol) {
    int i = blockIdx.x * 256 + threadIdx.x;
    int t = i >> 12, d = i & 4095;
    float v = f12[(size_t)t * F2W + d];
    float s = v / (1.0f + __expf(-v)) * f12[(size_t)t * F2W + 4096 + d];
    __half h = __float2half(s);
    oh[i] = h;
    ol[i] = __float2half(s - __half2float(h));
}

// ======================= mma.sync fp16 2-pass GEMM =======================
// C[M,N] = (Ah+Al)[M,K] @ Bh[N,K]^T : AhBh + AlBh.
// CTA tile 128x128, BK=32, 8 warps (warp tile 32x64), 3-stage cp.async, 2 CTAs/SM.
#define SSTG      24576          // Ah(8K) + Al(8K) + Bh(8K)
#define GSMEM     (3*SSTG)       // 72 KB

__device__ __forceinline__ uint32_t smem_u32(const void* p) {
    uint32_t a;
    asm("{ .reg .u64 t; cvta.to.shared.u64 t, %1; cvt.u32.u64 %0, t; }" : "=r"(a) : "l"(p));
    return a;
}
__device__ __forceinline__ void cp16(uint32_t s, const void* g) {
    asm volatile("cp.async.cg.shared.global [%0], [%1], 16;" :: "r"(s), "l"(g));
}
#define LDMX4(r0, r1, r2, r3, addr) \
    asm volatile("ldmatrix.sync.aligned.m8n8.x4.shared.b16 {%0,%1,%2,%3}, [%4];" \
        : "=r"(r0), "=r"(r1), "=r"(r2), "=r"(r3) : "r"(addr))
#define MMA16816(d, a, b) \
    asm volatile("mma.sync.aligned.m16n8k16.row.col.f32.f16.f16.f32 " \
        "{%0,%1,%2,%3}, {%4,%5,%6,%7}, {%8,%9}, {%0,%1,%2,%3};" \
        : "+f"((d)[0]), "+f"((d)[1]), "+f"((d)[2]), "+f"((d)[3]) \
        : "r"((a)[0]), "r"((a)[1]), "r"((a)[2]), "r"((a)[3]), "r"((b)[0]), "r"((b)[1]))

__device__ __forceinline__ void stage_load(uint32_t st,
                                           const __half* Ah, const __half* Al,
                                           const __half* Bh,
                                           int m0, int n0, int k0, int K, int tid) {
#pragma unroll
    for (int c = tid; c < 512; c += 256) {
        int r = c >> 2, u = c & 3;
        uint32_t off = r * 64 + ((u ^ ((r >> 1) & 3)) << 4);
        size_t ga = (size_t)(m0 + r) * K + k0 + u * 8;
        size_t gb = (size_t)(n0 + r) * K + k0 + u * 8;
        cp16(st + off,          Ah + ga);
        cp16(st + 8192  + off,  Al + ga);
        cp16(st + 16384 + off,  Bh + gb);
    }
    asm volatile("cp.async.commit_group;" ::: "memory");
}

__global__ __launch_bounds__(256, 2) void gemm_fp16(
    const __half* __restrict__ Ah, const __half* __restrict__ Al,
    const __half* __restrict__ Bh,
    float* __restrict__ C, int N, int K)
{
    extern __shared__ __align__(128) char smem[];
    const uint32_t sb = smem_u32(smem);
    const int tid = threadIdx.x;
    const int lane = tid & 31;
    const int w = tid >> 5;
    const int wm = w & 3;
    const int wn = w >> 2;
    const int m0 = blockIdx.x * 128;
    const int n0 = blockIdx.y * 128;
    const int niter = K >> 5;

    float acc[2][8][4] = {};

    stage_load(sb,        Ah, Al, Bh, m0, n0, 0,  K, tid);
    stage_load(sb + SSTG, Ah, Al, Bh, m0, n0, 32, K, tid);

    const int a_r = wm * 32 + (lane & 15);
    const int a_uadd = lane >> 4;
    const int b_mat = lane >> 3;
    const int b_r0 = wn * 64 + ((b_mat >> 1) << 3) + (lane & 7);
    const int b_uadd = b_mat & 1;

    for (int it = 0; it < niter; it++) {
        if (it + 2 < niter) { asm volatile("cp.async.wait_group 1;" ::: "memory"); }
        else                { asm volatile("cp.async.wait_group 0;" ::: "memory"); }
        __syncthreads();
        if (it + 2 < niter)
            stage_load(sb + ((it + 2) % 3) * SSTG, Ah, Al, Bh, m0, n0, (it + 2) * 32, K, tid);

        const uint32_t st = sb + (it % 3) * SSTG;
#pragma unroll
        for (int ks = 0; ks < 2; ks++) {
            uint32_t ah[2][4], al[2][4], bh[8][2];
#pragma unroll
            for (int mb = 0; mb < 2; mb++) {
                int r = a_r + mb * 16;
                int u = ks * 2 + a_uadd;
                uint32_t off = r * 64 + ((u ^ ((r >> 1) & 3)) << 4);
                LDMX4(ah[mb][0], ah[mb][1], ah[mb][2], ah[mb][3], st + off);
                LDMX4(al[mb][0], al[mb][1], al[mb][2], al[mb][3], st + 8192 + off);
            }
#pragma unroll
            for (int qd = 0; qd < 4; qd++) {
                int r = b_r0 + qd * 16;
                int u = ks * 2 + b_uadd;
                uint32_t off = r * 64 + ((u ^ ((r >> 1) & 3)) << 4);
                uint32_t t0, t1, t2, t3;
                LDMX4(t0, t1, t2, t3, st + 16384 + off);
                bh[2*qd][0] = t0; bh[2*qd][1] = t1; bh[2*qd+1][0] = t2; bh[2*qd+1][1] = t3;
            }
#pragma unroll
            for (int mb = 0; mb < 2; mb++)
#pragma unroll
                for (int nb = 0; nb < 8; nb++) {
                    MMA16816(acc[mb][nb], ah[mb], bh[nb]);
                    MMA16816(acc[mb][nb], al[mb], bh[nb]);
                }
        }
    }

#pragma unroll
    for (int mb = 0; mb < 2; mb++) {
        int row = m0 + wm * 32 + mb * 16 + (lane >> 2);
#pragma unroll
        for (int nb = 0; nb < 8; nb++) {
            int col = n0 + wn * 64 + nb * 8 + 2 * (lane & 3);
            *(float2*)(C + (size_t)row * N + col)       = make_float2(acc[mb][nb][0], acc[mb][nb][1]);
            *(float2*)(C + (size_t)(row + 8) * N + col) = make_float2(acc[mb][nb][2], acc[mb][nb][3]);
        }
    }
}

// ======================= host driver =======================
extern "C" void kernel_launch(void* const* d_in, const int* in_sizes, int n_in,
                              void* d_out, int out_size) {
    const int*   ids = (const int*)  d_in[0];
    const float* emb = (const float*)d_in[1];
    const float* Wq  = (const float*)d_in[2];
    const float* Wk  = (const float*)d_in[3];
    const float* Wv  = (const float*)d_in[4];
    const float* Wo  = (const float*)d_in[5];
    const float* W1  = (const float*)d_in[6];
    const float* W2  = (const float*)d_in[7];
    const float* W3  = (const float*)d_in[8];
    const float* n1  = (const float*)d_in[9];
    const float* n2  = (const float*)d_in[10];
    const float* n3  = (const float*)d_in[11];
    const float* n4  = (const float*)d_in[12];
    const float* qn  = (const float*)d_in[13];
    const float* kn  = (const float*)d_in[14];
    const float* nf  = (const float*)d_in[15];
    const float* cosb = (const float*)d_in[16];
    const float* sinb = (const float*)d_in[17];
    float* out = (float*)d_out;

    float *x, *qkv, *t, *f12;
    cudaGetSymbolAddress((void**)&x,   g_x);
    cudaGetSymbolAddress((void**)&qkv, g_qkv);
    cudaGetSymbolAddress((void**)&t,   g_t);
    cudaGetSymbolAddress((void**)&f12, g_f12);

    __half *ah, *al, *wqkv, *wo, *w12, *w3, *eh;
    cudaGetSymbolAddress((void**)&ah,   g_a_h);
    cudaGetSymbolAddress((void**)&al,   g_a_l);
    cudaGetSymbolAddress((void**)&wqkv, g_wqkv);
    cudaGetSymbolAddress((void**)&wo,   g_wot);
    cudaGetSymbolAddress((void**)&w12,  g_w12);
    cudaGetSymbolAddress((void**)&w3,   g_w3t);
    cudaGetSymbolAddress((void**)&eh,   g_emb);

    cudaFuncSetAttribute(gemm_fp16, cudaFuncAttributeMaxDynamicSharedMemorySize, GSMEM);
    cudaFuncSetAttribute(flash_attn, cudaFuncAttributeMaxDynamicSharedMemorySize, FA_SMEM);

    // weight conversion (transpose into packed fp16 layouts)
    dim3 wb(32, 8);
    wconv_kernel<<<dim3(1024/32, 1024/32, NL), wb>>>(Wq, wqkv, 1024, 1024, (size_t)QKVW*1024, 0);
    wconv_kernel<<<dim3(256/32,  1024/32, NL), wb>>>(Wk, wqkv, 1024, 256,  (size_t)QKVW*1024, 1024);
    wconv_kernel<<<dim3(256/32,  1024/32, NL), wb>>>(Wv, wqkv, 1024, 256,  (size_t)QKVW*1024, 1280);
    wconv_kernel<<<dim3(1024/32, 1024/32, NL), wb>>>(Wo, wo,  1024, 1024, (size_t)1024*1024, 0);
    wconv_kernel<<<dim3(4096/32, 1024/32, NL), wb>>>(W1, w12, 1024, 4096, (size_t)F2W*1024, 0);
    wconv_kernel<<<dim3(4096/32, 1024/32, NL), wb>>>(W2, w12, 1024, 4096, (size_t)F2W*1024, 4096);
    wconv_kernel<<<dim3(1024/32, 4096/32, NL), wb>>>(W3, w3,  4096, 1024, (size_t)4096*1024, 0);
    half_kernel<<<(VOCAB*DIM)/256, 256>>>(emb, eh, VOCAB*DIM);

    embed_kernel<<<NTOK, 256>>>(ids, emb, x);

    const int MT = NTOK / 128;   // 32

    for (int l = 0; l < NL; l++) {
        const int window = (l < NL - 4) ? WIN : 0;

        rmsnorm_split_kernel<<<NTOK, 256>>>(x, n1 + (size_t)l * DIM, ah, al);

        gemm_fp16<<<dim3(MT, QKVW/128), 256, GSMEM>>>(ah, al,
            wqkv + (size_t)l*QKVW*1024, qkv, QKVW, 1024);

        qkrope_kernel<<<dim3(NTOK, NH), 64>>>(qkv, qn + (size_t)l * HDIM, cosb, sinb, 0);
        qkrope_kernel<<<dim3(NTOK, NG), 64>>>(qkv, kn + (size_t)l * HDIM, cosb, sinb, 1024);

        flash_attn<<<dim3(SEQ/64, BATCH, NH), 256, FA_SMEM>>>(qkv, ah, al, window);

        gemm_fp16<<<dim3(MT, 1024/128), 256, GSMEM>>>(ah, al,
            wo + (size_t)l*1024*1024, t, 1024, 1024);
        addrms_kernel<<<NTOK, 256>>>(x, t, n2 + (size_t)l * DIM);

        rmsnorm_split_kernel<<<NTOK, 256>>>(x, n3 + (size_t)l * DIM, ah, al);
        gemm_fp16<<<dim3(MT, F2W/128), 256, GSMEM>>>(ah, al,
            w12 + (size_t)l*F2W*1024, f12, F2W, 1024);
        silu_split_kernel<<<(NTOK*FF)/256, 256>>>(f12, ah, al);
        gemm_fp16<<<dim3(MT, 1024/128), 256, GSMEM>>>(ah, al,
            w3 + (size_t)l*1024*4096, t, 1024, 4096);
        addrms_kernel<<<NTOK, 256>>>(x, t, n4 + (size_t)l * DIM);
    }

    rmsnorm_split_kernel<<<NTOK, 256>>>(x, nf, ah, al);
    gemm_fp16<<<dim3(MT, VOCAB/128), 256, GSMEM>>>(ah, al, eh, out, VOCAB, 1024);
}

// round 7
// speedup vs baseline: 3.5427x; 1.0004x over previous
#include <cuda_runtime.h>
#include <cuda_fp16.h>
#include <math.h>
#include <stdint.h>

#define BATCH  2
#define SEQ    2048
#define DIM    1024
#define NH     16
#define NG     4
#define GRP    4
#define HDIM   64
#define FF     4096
#define NL     8
#define VOCAB  32000
#define WIN    1024
#define EPS    1e-6f
#define NTOK   (BATCH*SEQ)   // 4096
#define QKVW   1536
#define F2W    8192

// ======================= scratch =======================
__device__ float g_x   [NTOK*DIM];
__device__ float g_qkv [NTOK*QKVW];
__device__ float g_t   [NTOK*DIM];

__device__ __align__(128) __half g_a_h[NTOK*DIM];   // activations (K=1024 operands)
__device__ __align__(128) __half g_a_l[NTOK*DIM];
__device__ __align__(128) __half g_b_h[NTOK*FF];    // FFN intermediate (K=4096 operand)
__device__ __align__(128) __half g_b_l[NTOK*FF];
__device__ __align__(128) __half g_wqkv[NL*QKVW*1024];
__device__ __align__(128) __half g_wot [NL*1024*1024];
__device__ __align__(128) __half g_w12 [NL*F2W*1024];
__device__ __align__(128) __half g_w3t [NL*1024*4096];
__device__ __align__(128) __half g_emb [VOCAB*DIM];

// ======================= small kernels =======================
__global__ void embed_kernel(const int* __restrict__ ids,
                             const float* __restrict__ emb,
                             float* __restrict__ x) {
    int t = blockIdx.x;
    int id = ids[t];
    const float* e = emb + (size_t)id * DIM;
    float* xp = x + (size_t)t * DIM;
    for (int d = threadIdx.x; d < DIM; d += blockDim.x)
        xp[d] = e[d] * 32.0f;
}

__global__ void half_kernel(const float* __restrict__ in,
                            __half* __restrict__ o, int n) {
    int i = blockIdx.x * 256 + threadIdx.x;
    if (i < n) o[i] = __float2half(in[i]);
}

// transpose to fp16 packed: W [L,K,N] fp32 -> out [L, prow(n), K]
// mode 0: prow = rowoff + n
// mode 1: prow = ((n>>6)<<7) + (n&63)        (W1 interleave)
// mode 2: prow = ((n>>6)<<7) + 64 + (n&63)   (W2 interleave)
__global__ void wconv_kernel(const float* __restrict__ W,
                             __half* __restrict__ o,
                             int K, int N, size_t lstride, int rowoff, int mode) {
    __shared__ float t[32][33];
    int l = blockIdx.z;
    const float* Wl = W + (size_t)l * K * N;
    size_t ob = (size_t)l * lstride;
    int n0 = blockIdx.x * 32, k0 = blockIdx.y * 32;
    int tx = threadIdx.x, ty = threadIdx.y;
#pragma unroll
    for (int r = 0; r < 32; r += 8)
        t[ty + r][tx] = Wl[(size_t)(k0 + ty + r) * N + n0 + tx];
    __syncthreads();
#pragma unroll
    for (int r = 0; r < 32; r += 8) {
        int n = n0 + ty + r;
        int prow;
        if (mode == 0)      prow = rowoff + n;
        else if (mode == 1) prow = ((n >> 6) << 7) + (n & 63);
        else                prow = ((n >> 6) << 7) + 64 + (n & 63);
        o[ob + (size_t)prow * K + k0 + tx] = __float2half(t[tx][ty + r]);
    }
}

__global__ __launch_bounds__(256) void rmsnorm_split_kernel(const float* __restrict__ in,
                                                            const float* __restrict__ scale,
                                                            __half* __restrict__ oh,
                                                            __half* __restrict__ ol) {
    const int t = blockIdx.x;
    const float* xp = in + (size_t)t * DIM;
    float ss = 0.f;
    for (int d = threadIdx.x; d < DIM; d += 256) { float v = xp[d]; ss += v * v; }
    __shared__ float red[256];
    red[threadIdx.x] = ss; __syncthreads();
    for (int o = 128; o > 0; o >>= 1) {
        if (threadIdx.x < o) red[threadIdx.x] += red[threadIdx.x + o];
        __syncthreads();
    }
    const float r = rsqrtf(red[0] * (1.0f / DIM) + EPS);
    for (int d = threadIdx.x; d < DIM; d += 256) {
        float v = xp[d] * r * (1.0f + scale[d]);
        __half h = __float2half(v);
        oh[(size_t)t * DIM + d] = h;
        ol[(size_t)t * DIM + d] = __float2half(v - __half2float(h));
    }
}

// x += rmsnorm(t, sa); then out = rmsnorm(x, so) -> split fp16
__global__ __launch_bounds__(256) void fuse_norm_kernel(float* __restrict__ x,
                                                        const float* __restrict__ t,
                                                        const float* __restrict__ sa,
                                                        const float* __restrict__ so,
                                                        __half* __restrict__ oh,
                                                        __half* __restrict__ ol) {
    const int tk = blockIdx.x;
    const float* tp = t + (size_t)tk * DIM;
    float* xp = x + (size_t)tk * DIM;
    float tv[4], xv[4];
    float ss = 0.f;
    __shared__ float red[256];
#pragma unroll
    for (int i = 0; i < 4; i++) {
        int d = threadIdx.x + 256 * i;
        tv[i] = tp[d];
        ss += tv[i] * tv[i];
    }
    red[threadIdx.x] = ss; __syncthreads();
    for (int o = 128; o > 0; o >>= 1) {
        if (threadIdx.x < o) red[threadIdx.x] += red[threadIdx.x + o];
        __syncthreads();
    }
    const float r1 = rsqrtf(red[0] * (1.0f / DIM) + EPS);
    __syncthreads();
    float ss2 = 0.f;
#pragma unroll
    for (int i = 0; i < 4; i++) {
        int d = threadIdx.x + 256 * i;
        xv[i] = xp[d] + tv[i] * r1 * (1.0f + sa[d]);
        ss2 += xv[i] * xv[i];
        xp[d] = xv[i];
    }
    red[threadIdx.x] = ss2; __syncthreads();
    for (int o = 128; o > 0; o >>= 1) {
        if (threadIdx.x < o) red[threadIdx.x] += red[threadIdx.x + o];
        __syncthreads();
    }
    const float r2 = rsqrtf(red[0] * (1.0f / DIM) + EPS);
#pragma unroll
    for (int i = 0; i < 4; i++) {
        int d = threadIdx.x + 256 * i;
        float v = xv[i] * r2 * (1.0f + so[d]);
        __half h = __float2half(v);
        oh[(size_t)tk * DIM + d] = h;
        ol[(size_t)tk * DIM + d] = __float2half(v - __half2float(h));
    }
}

// merged q+k rmsnorm+rope: blockIdx.y in [0, NH+NG)
__global__ __launch_bounds__(64) void qkrope_kernel(float* __restrict__ x,
                                                    const float* __restrict__ qsc,
                                                    const float* __restrict__ ksc,
                                                    const float* __restrict__ cosb,
                                                    const float* __restrict__ sinb) {
    const int token = blockIdx.x;
    const int hh = blockIdx.y;
    const int pos = token % SEQ;
    const int d = threadIdx.x;
    const float* scale = (hh < NH) ? qsc : ksc;
    const int off = (hh < NH) ? hh * HDIM : 1024 + (hh - NH) * HDIM;
    float* xp = x + (size_t)token * QKVW + off;
    const float val = xp[d];
    __shared__ float sh[HDIM];
    sh[d] = val * val;
    __syncthreads();
    for (int o = 32; o > 0; o >>= 1) {
        if (d < o) sh[d] += sh[d + o];
        __syncthreads();
    }
    const float r = rsqrtf(sh[0] * (1.0f / HDIM) + EPS);
    __syncthreads();
    const float nv = val * r * (1.0f + scale[d]);
    sh[d] = nv;
    __syncthreads();
    const float rot = (d < 32) ? -sh[d + 32] : sh[d - 32];
    xp[d] = nv * cosb[pos * HDIM + d] + rot * sinb[pos * HDIM + d];
}

// ======================= flash attention (fp32, 64q x 64k tiles) =======================
#define APAD 68
#define FA_SMEM ((3*64*APAD + 64*65 + 3*64) * 4)

__global__ __launch_bounds__(256, 3) void flash_attn(const float* __restrict__ qkv,
                                                     __half* __restrict__ oh,
                                                     __half* __restrict__ ol,
                                                     int window) {
    extern __shared__ float sm[];
    float* qs    = sm;
    float* ks    = qs + 64 * APAD;
    float* vs    = ks + 64 * APAD;
    float* sc    = vs + 64 * APAD;
    float* mrun  = sc + 64 * 65;
    float* srun  = mrun + 64;
    float* alpha = srun + 64;

    const int qt = blockIdx.x, b = blockIdx.y, h = blockIdx.z;
    const int g = h / GRP;
    const int tid = threadIdx.x;
    const int q0 = qt * 64;
    const int w = tid >> 5, lane = tid & 31;
    const int av_q = tid >> 2;
    const int av_d = (tid & 3) * 16;

    for (int i = tid; i < 64 * 16; i += 256) {
        int r = i >> 4, c4 = (i & 15) << 2;
        float4 v4 = *(const float4*)(qkv + (size_t)(b * SEQ + q0 + r) * QKVW + h * HDIM + c4);
        v4.x *= 0.125f; v4.y *= 0.125f; v4.z *= 0.125f; v4.w *= 0.125f;
        *(float4*)&qs[r * APAD + c4] = v4;
    }
    if (tid < 64) { mrun[tid] = -1e30f; srun[tid] = 0.f; }
    float out[16] = {};

    int t0 = 0;
    if (window > 0) { int lo = q0 - window; if (lo > 0) t0 = lo >> 6; }

    for (int kt = t0; kt <= qt; kt++) {
        __syncthreads();
        const int k0 = kt * 64;
        for (int i = tid; i < 64 * 16; i += 256) {
            int r = i >> 4, c4 = (i & 15) << 2;
            size_t base = (size_t)(b * SEQ + k0 + r) * QKVW + g * HDIM + c4;
            *(float4*)&ks[r * APAD + c4] = *(const float4*)(qkv + base + 1024);
            *(float4*)&vs[r * APAD + c4] = *(const float4*)(qkv + base + 1280);
        }
        __syncthreads();

        float s1[8], s2[8];
#pragma unroll
        for (int i = 0; i < 8; i++) { s1[i] = 0.f; s2[i] = 0.f; }
#pragma unroll 4
        for (int d4 = 0; d4 < 16; d4++) {
            float4 k1 = *(float4*)&ks[lane * APAD + d4 * 4];
            float4 k2 = *(float4*)&ks[(lane + 32) * APAD + d4 * 4];
#pragma unroll
            for (int qq = 0; qq < 8; qq++) {
                float4 qv = *(float4*)&qs[(w * 8 + qq) * APAD + d4 * 4];
                s1[qq] += qv.x * k1.x + qv.y * k1.y + qv.z * k1.z + qv.w * k1.w;
                s2[qq] += qv.x * k2.x + qv.y * k2.y + qv.z * k2.z + qv.w * k2.w;
            }
        }
        const int j1 = k0 + lane, j2 = k0 + lane + 32;
#pragma unroll
        for (int qq = 0; qq < 8; qq++) {
            const int ql = w * 8 + qq;
            const int qi = q0 + ql;
            bool v1 = (j1 <= qi) && (window == 0 || qi - j1 <= window);
            bool v2 = (j2 <= qi) && (window == 0 || qi - j2 <= window);
            float a = v1 ? s1[qq] : -1e30f;
            float c = v2 ? s2[qq] : -1e30f;
            float mx = fmaxf(a, c);
#pragma unroll
            for (int o = 16; o > 0; o >>= 1)
                mx = fmaxf(mx, __shfl_xor_sync(0xffffffffu, mx, o));
            const float mold = mrun[ql];
            const float mnew = fmaxf(mold, mx);
            float p1 = v1 ? __expf(a - mnew) : 0.f;
            float p2 = v2 ? __expf(c - mnew) : 0.f;
            float ps = p1 + p2;
#pragma unroll
            for (int o = 16; o > 0; o >>= 1)
                ps += __shfl_xor_sync(0xffffffffu, ps, o);
            if (lane == 0) {
                const float al_ = __expf(mold - mnew);
                mrun[ql] = mnew;
                srun[ql] = srun[ql] * al_ + ps;
                alpha[ql] = al_;
            }
            sc[ql * 65 + lane]      = p1;
            sc[ql * 65 + lane + 32] = p2;
        }
        __syncthreads();

        const float al_ = alpha[av_q];
#pragma unroll
        for (int i = 0; i < 16; i++) out[i] *= al_;
        for (int kk = 0; kk < 64; kk++) {
            const float wgt = sc[av_q * 65 + kk];
            const float* vp = &vs[kk * APAD + av_d];
#pragma unroll
            for (int i = 0; i < 16; i += 4) {
                float4 v4 = *(const float4*)(vp + i);
                out[i]     += wgt * v4.x;
                out[i + 1] += wgt * v4.y;
                out[i + 2] += wgt * v4.z;
                out[i + 3] += wgt * v4.w;
            }
        }
    }
    __syncthreads();
    const float inv = 1.0f / srun[av_q];
    size_t obase = (size_t)(b * SEQ + q0 + av_q) * (NH * HDIM) + h * HDIM + av_d;
#pragma unroll
    for (int i = 0; i < 16; i++) {
        float o = out[i] * inv;
        __half hv = __float2half(o);
        oh[obase + i] = hv;
        ol[obase + i] = __float2half(o - __half2float(hv));
    }
}

// ======================= mma.sync fp16 2-pass GEMM, 4-stage + frag double-buffer =======================
#define SSTG      24576
#define NSTAGE    4
#define GSMEM     (NSTAGE*SSTG)   // 96 KB

__device__ __forceinline__ uint32_t smem_u32(const void* p) {
    uint32_t a;
    asm("{ .reg .u64 t; cvta.to.shared.u64 t, %1; cvt.u32.u64 %0, t; }" : "=r"(a) : "l"(p));
    return a;
}
__device__ __forceinline__ void cp16(uint32_t s, const void* g) {
    asm volatile("cp.async.cg.shared.global [%0], [%1], 16;" :: "r"(s), "l"(g));
}
#define LDMX4(r0, r1, r2, r3, addr) \
    asm volatile("ldmatrix.sync.aligned.m8n8.x4.shared.b16 {%0,%1,%2,%3}, [%4];" \
        : "=r"(r0), "=r"(r1), "=r"(r2), "=r"(r3) : "r"(addr))
#define MMA16816(d, a, b) \
    asm volatile("mma.sync.aligned.m16n8k16.row.col.f32.f16.f16.f32 " \
        "{%0,%1,%2,%3}, {%4,%5,%6,%7}, {%8,%9}, {%0,%1,%2,%3};" \
        : "+f"((d)[0]), "+f"((d)[1]), "+f"((d)[2]), "+f"((d)[3]) \
        : "r"((a)[0]), "r"((a)[1]), "r"((a)[2]), "r"((a)[3]), "r"((b)[0]), "r"((b)[1]))

struct Frag {
    uint32_t a[2][2][4];   // [limb][mb][reg]
    uint32_t b[8][2];
};

__device__ __forceinline__ void load_frags(Frag& f, uint32_t st, int ks,
                                           int a_r, int a_uadd, int b_r0, int b_uadd) {
#pragma unroll
    for (int mb = 0; mb < 2; mb++) {
        int r = a_r + mb * 16;
        int u = ks * 2 + a_uadd;
        uint32_t off = r * 64 + ((u ^ ((r >> 1) & 3)) << 4);
        LDMX4(f.a[0][mb][0], f.a[0][mb][1], f.a[0][mb][2], f.a[0][mb][3], st + off);
        LDMX4(f.a[1][mb][0], f.a[1][mb][1], f.a[1][mb][2], f.a[1][mb][3], st + 8192 + off);
    }
#pragma unroll
    for (int qd = 0; qd < 4; qd++) {
        int r = b_r0 + qd * 16;
        int u = ks * 2 + b_uadd;
        uint32_t off = r * 64 + ((u ^ ((r >> 1) & 3)) << 4);
        uint32_t t0, t1, t2, t3;
        LDMX4(t0, t1, t2, t3, st + 16384 + off);
        f.b[2*qd][0] = t0; f.b[2*qd][1] = t1;
        f.b[2*qd+1][0] = t2; f.b[2*qd+1][1] = t3;
    }
}

__device__ __forceinline__ void do_mma(float acc[2][8][4], const Frag& f) {
#pragma unroll
    for (int mb = 0; mb < 2; mb++)
#pragma unroll
        for (int nb = 0; nb < 8; nb++) {
            MMA16816(acc[mb][nb], f.a[0][mb], f.b[nb]);
            MMA16816(acc[mb][nb], f.a[1][mb], f.b[nb]);
        }
}

__device__ __forceinline__ void stage_load(uint32_t st,
                                           const __half* Ah, const __half* Al,
                                           const __half* Bh,
                                           int m0, int n0, int k0, int K, int tid) {
#pragma unroll
    for (int c = tid; c < 512; c += 256) {
        int r = c >> 2, u = c & 3;
        uint32_t off = r * 64 + ((u ^ ((r >> 1) & 3)) << 4);
        size_t ga = (size_t)(m0 + r) * K + k0 + u * 8;
        size_t gb = (size_t)(n0 + r) * K + k0 + u * 8;
        cp16(st + off,          Ah + ga);
        cp16(st + 8192  + off,  Al + ga);
        cp16(st + 16384 + off,  Bh + gb);
    }
    asm volatile("cp.async.commit_group;" ::: "memory");
}

// silu=0: C[M,N] (fp32). silu=1: interleaved [64 W1|64 W2] tiles -> silu -> oh/ol fp16.
__global__ __launch_bounds__(256) void gemm_fp16(
    const __half* __restrict__ Ah, const __half* __restrict__ Al,
    const __half* __restrict__ Bh,
    float* __restrict__ C, __half* __restrict__ oh, __half* __restrict__ ol,
    int N, int K, int silu)
{
    extern __shared__ __align__(128) char smem[];
    const uint32_t sb = smem_u32(smem);
    const int tid = threadIdx.x;
    const int lane = tid & 31;
    const int w = tid >> 5;
    const int wm = w & 3;
    const int wn = w >> 2;
    const int m0 = blockIdx.x * 128;
    const int n0 = blockIdx.y * 128;
    const int niter = K >> 5;

    float acc[2][8][4] = {};
    Frag f0, f1;

    stage_load(sb + 0*SSTG, Ah, Al, Bh, m0, n0, 0,  K, tid);
    stage_load(sb + 1*SSTG, Ah, Al, Bh, m0, n0, 32, K, tid);
    stage_load(sb + 2*SSTG, Ah, Al, Bh, m0, n0, 64, K, tid);

    const int a_r = wm * 32 + (lane & 15);
    const int a_uadd = lane >> 4;
    const int b_mat = lane >> 3;
    const int b_r0 = wn * 64 + ((b_mat >> 1) << 3) + (lane & 7);
    const int b_uadd = b_mat & 1;

    asm volatile("cp.async.wait_group 1;" ::: "memory");
    __syncthreads();
    load_frags(f0, sb, 0, a_r, a_uadd, b_r0, b_uadd);

    for (int it = 0; it < niter; it++) {
        const uint32_t st  = sb + (it & 3) * SSTG;
        const uint32_t stn = sb + ((it + 1) & 3) * SSTG;

        load_frags(f1, st, 1, a_r, a_uadd, b_r0, b_uadd);
        do_mma(acc, f0);
        if (it + 1 < niter)
            load_frags(f0, stn, 0, a_r, a_uadd, b_r0, b_uadd);
        do_mma(acc, f1);

        if ((it + 3) * 32 < K) {
            stage_load(sb + ((it + 3) & 3) * SSTG, Ah, Al, Bh, m0, n0, (it + 3) * 32, K, tid);
            asm volatile("cp.async.wait_group 1;" ::: "memory");
        } else {
            asm volatile("cp.async.wait_group 0;" ::: "memory");
        }
        __syncthreads();
    }

    if (!silu) {
#pragma unroll
        for (int mb = 0; mb < 2; mb++) {
            int row = m0 + wm * 32 + mb * 16 + (lane >> 2);
#pragma unroll
            for (int nb = 0; nb < 8; nb++) {
                int col = n0 + wn * 64 + nb * 8 + 2 * (lane & 3);
                *(float2*)(C + (size_t)row * N + col)       = make_float2(acc[mb][nb][0], acc[mb][nb][1]);
                *(float2*)(C + (size_t)(row + 8) * N + col) = make_float2(acc[mb][nb][2], acc[mb][nb][3]);
            }
        }
    } else {
        float* smf = (float*)smem;   // 128 x 132
#pragma unroll
        for (int mb = 0; mb < 2; mb++) {
            int rl = wm * 32 + mb * 16 + (lane >> 2);
#pragma unroll
            for (int nb = 0; nb < 8; nb++) {
                int cl = wn * 64 + nb * 8 + 2 * (lane & 3);
                smf[rl * 132 + cl]           = acc[mb][nb][0];
                smf[rl * 132 + cl + 1]       = acc[mb][nb][1];
                smf[(rl + 8) * 132 + cl]     = acc[mb][nb][2];
                smf[(rl + 8) * 132 + cl + 1] = acc[mb][nb][3];
            }
        }
        __syncthreads();
        for (int i = tid; i < 128 * 64; i += 256) {
            int r = i >> 6, c = i & 63;
            float v1 = smf[r * 132 + c];
            float v2 = smf[r * 132 + c + 64];
            float s = v1 / (1.0f + __expf(-v1)) * v2;
            size_t o = (size_t)(m0 + r) * FF + (size_t)blockIdx.y * 64 + c;
            __half hv = __float2half(s);
            oh[o] = hv;
            ol[o] = __float2half(s - __half2float(hv));
        }
    }
}

// ======================= host driver =======================
extern "C" void kernel_launch(void* const* d_in, const int* in_sizes, int n_in,
                              void* d_out, int out_size) {
    const int*   ids = (const int*)  d_in[0];
    const float* emb = (const float*)d_in[1];
    const float* Wq  = (const float*)d_in[2];
    const float* Wk  = (const float*)d_in[3];
    const float* Wv  = (const float*)d_in[4];
    const float* Wo  = (const float*)d_in[5];
    const float* W1  = (const float*)d_in[6];
    const float* W2  = (const float*)d_in[7];
    const float* W3  = (const float*)d_in[8];
    const float* n1  = (const float*)d_in[9];
    const float* n2  = (const float*)d_in[10];
    const float* n3  = (const float*)d_in[11];
    const float* n4  = (const float*)d_in[12];
    const float* qn  = (const float*)d_in[13];
    const float* kn  = (const float*)d_in[14];
    const float* nf  = (const float*)d_in[15];
    const float* cosb = (const float*)d_in[16];
    const float* sinb = (const float*)d_in[17];
    float* out = (float*)d_out;

    float *x, *qkv, *t;
    cudaGetSymbolAddress((void**)&x,   g_x);
    cudaGetSymbolAddress((void**)&qkv, g_qkv);
    cudaGetSymbolAddress((void**)&t,   g_t);

    __half *ah, *al, *bh, *bl, *wqkv, *wo, *w12, *w3, *eh;
    cudaGetSymbolAddress((void**)&ah,   g_a_h);
    cudaGetSymbolAddress((void**)&al,   g_a_l);
    cudaGetSymbolAddress((void**)&bh,   g_b_h);
    cudaGetSymbolAddress((void**)&bl,   g_b_l);
    cudaGetSymbolAddress((void**)&wqkv, g_wqkv);
    cudaGetSymbolAddress((void**)&wo,   g_wot);
    cudaGetSymbolAddress((void**)&w12,  g_w12);
    cudaGetSymbolAddress((void**)&w3,   g_w3t);
    cudaGetSymbolAddress((void**)&eh,   g_emb);

    cudaFuncSetAttribute(gemm_fp16, cudaFuncAttributeMaxDynamicSharedMemorySize, GSMEM);
    cudaFuncSetAttribute(flash_attn, cudaFuncAttributeMaxDynamicSharedMemorySize, FA_SMEM);

    // weight conversion
    dim3 wb(32, 8);
    wconv_kernel<<<dim3(1024/32, 1024/32, NL), wb>>>(Wq, wqkv, 1024, 1024, (size_t)QKVW*1024, 0,    0);
    wconv_kernel<<<dim3(256/32,  1024/32, NL), wb>>>(Wk, wqkv, 1024, 256,  (size_t)QKVW*1024, 1024, 0);
    wconv_kernel<<<dim3(256/32,  1024/32, NL), wb>>>(Wv, wqkv, 1024, 256,  (size_t)QKVW*1024, 1280, 0);
    wconv_kernel<<<dim3(1024/32, 1024/32, NL), wb>>>(Wo, wo,  1024, 1024, (size_t)1024*1024, 0, 0);
    wconv_kernel<<<dim3(4096/32, 1024/32, NL), wb>>>(W1, w12, 1024, 4096, (size_t)F2W*1024, 0, 1);
    wconv_kernel<<<dim3(4096/32, 1024/32, NL), wb>>>(W2, w12, 1024, 4096, (size_t)F2W*1024, 0, 2);
    wconv_kernel<<<dim3(1024/32, 4096/32, NL), wb>>>(W3, w3,  4096, 1024, (size_t)4096*1024, 0, 0);
    half_kernel<<<(VOCAB*DIM)/256, 256>>>(emb, eh, VOCAB*DIM);

    embed_kernel<<<NTOK, 256>>>(ids, emb, x);
    rmsnorm_split_kernel<<<NTOK, 256>>>(x, n1, ah, al);   // layer 0 pre-norm

    const int MT = NTOK / 128;   // 32

    for (int l = 0; l < NL; l++) {
        const int window = (l < NL - 4) ? WIN : 0;

        gemm_fp16<<<dim3(MT, QKVW/128), 256, GSMEM>>>(ah, al,
            wqkv + (size_t)l*QKVW*1024, qkv, nullptr, nullptr, QKVW, 1024, 0);

        qkrope_kernel<<<dim3(NTOK, NH+NG), 64>>>(qkv, qn + (size_t)l * HDIM,
                                                 kn + (size_t)l * HDIM, cosb, sinb);

        flash_attn<<<dim3(SEQ/64, BATCH, NH), 256, FA_SMEM>>>(qkv, ah, al, window);

        gemm_fp16<<<dim3(MT, 1024/128), 256, GSMEM>>>(ah, al,
            wo + (size_t)l*1024*1024, t, nullptr, nullptr, 1024, 1024, 0);

        fuse_norm_kernel<<<NTOK, 256>>>(x, t, n2 + (size_t)l * DIM,
                                        n3 + (size_t)l * DIM, ah, al);

        // W12 GEMM reads ah/al, writes FFN intermediate to bh/bl (no aliasing)
        gemm_fp16<<<dim3(MT, F2W/128), 256, GSMEM>>>(ah, al,
            w12 + (size_t)l*F2W*1024, nullptr, bh, bl, F2W, 1024, 1);

        gemm_fp16<<<dim3(MT, 1024/128), 256, GSMEM>>>(bh, bl,
            w3 + (size_t)l*1024*4096, t, nullptr, nullptr, 1024, 4096, 0);

        const float* so = (l < NL - 1) ? (n1 + (size_t)(l+1) * DIM) : nf;
        fuse_norm_kernel<<<NTOK, 256>>>(x, t, n4 + (size_t)l * DIM, so, ah, al);
    }

    gemm_fp16<<<dim3(MT, VOCAB/128), 256, GSMEM>>>(ah, al, eh, out,
                                                   nullptr, nullptr, VOCAB, 1024, 0);
}